// round 7
// baseline (speedup 1.0000x reference)
#include <cuda_runtime.h>
#include <cuda_bf16.h>
#include <math.h>
#include <stdint.h>

#define HB 4
#define CC 192
#define HW 65536
#define HW2 16384
#define HEADS 6
#define CHD 32

typedef unsigned short u16;

// ---------------- static scratch ----------------
__device__ float g_A[100663296];      // 402 MB
__device__ float g_B[100663296];      // 402 MB
__device__ u16   g_Xh[50331648];      // x bf16 hi plane (96 MB)
__device__ u16   g_Xl[50331648];      // x bf16 lo plane
__device__ u16   g_Wh[393216];        // all weights, padded rows, hi
__device__ u16   g_Wl[393216];
__device__ float g_invq[768];
__device__ float g_invk[768];
__device__ float g_S[24 * 1024];
__device__ float g_A0[24 * 1024];
__device__ float g_part[32 * 24 * 1024];

// weight plane offsets (u16 units), rows padded to grid.y*128, IC=192
#define WO_Q0    0         // 256 rows
#define WO_KV0   49152     // 384 rows
#define WO_Q1    122880    // 256
#define WO_KV1   172032    // 384
#define WO_P0    245760    // 256
#define WO_P1    294912    // 256
#define WO_DS    344064    // 256

// ================= helpers =================
__device__ __forceinline__ u16 bfb(float v) {
    __nv_bfloat16 b = __float2bfloat16(v);
    return *(u16*)&b;
}
__device__ __forceinline__ float bff(u16 s) {
    __nv_bfloat16 b = *(__nv_bfloat16*)&s;
    return __bfloat162float(b);
}
__device__ __forceinline__ uint32_t smem_u32(const void* p) {
    uint32_t a;
    asm("{ .reg .u64 t; cvta.to.shared.u64 t, %1; cvt.u32.u64 %0, t; }" : "=r"(a) : "l"(p));
    return a;
}
__device__ __forceinline__ void mma16816(float* d, const uint32_t* a, const uint32_t* b) {
    asm volatile(
        "mma.sync.aligned.m16n8k16.row.col.f32.bf16.bf16.f32 "
        "{%0,%1,%2,%3}, {%4,%5,%6,%7}, {%8,%9}, {%0,%1,%2,%3};"
        : "+f"(d[0]), "+f"(d[1]), "+f"(d[2]), "+f"(d[3])
        : "r"(a[0]), "r"(a[1]), "r"(a[2]), "r"(a[3]), "r"(b[0]), "r"(b[1]));
}
__device__ __forceinline__ void ldsm4(uint32_t* r, uint32_t addr) {
    asm volatile("ldmatrix.sync.aligned.m8n8.x4.shared.b16 {%0,%1,%2,%3}, [%4];"
        : "=r"(r[0]), "=r"(r[1]), "=r"(r[2]), "=r"(r[3]) : "r"(addr));
}
__device__ __forceinline__ void ldsm4t(uint32_t* r, uint32_t addr) {
    asm volatile("ldmatrix.sync.aligned.m8n8.x4.trans.shared.b16 {%0,%1,%2,%3}, [%4];"
        : "=r"(r[0]), "=r"(r[1]), "=r"(r[2]), "=r"(r[3]) : "r"(addr));
}
__device__ __forceinline__ void cpa16(uint32_t dst, const void* src) {
    asm volatile("cp.async.cg.shared.global [%0], [%1], 16;" :: "r"(dst), "l"(src));
}
#define CP_COMMIT() asm volatile("cp.async.commit_group;" ::: "memory")
#define CP_WAIT0()  asm volatile("cp.async.wait_group 0;" ::: "memory")
#define CP_WAIT1()  asm volatile("cp.async.wait_group 1;" ::: "memory")

// fast exp via FMA-pipe polynomial (inputs <= 0 after max-subtraction)
__device__ __forceinline__ float fexp(float x) {
    float t = x * 1.44269504089f;
    t = fmaxf(t, -126.f);
    float fi = rintf(t);
    float f = t - fi;
    float p = 0.00015403530393f;
    p = fmaf(p, f, 0.00133335581464f);
    p = fmaf(p, f, 0.00961812910763f);
    p = fmaf(p, f, 0.05550410866482f);
    p = fmaf(p, f, 0.24022650695910f);
    p = fmaf(p, f, 0.69314718055995f);
    p = fmaf(p, f, 1.0f);
    int i = (int)fi;
    float s = __int_as_float((i + 127) << 23);
    return p * s;
}

// ---------------- conversion kernels ----------------
__global__ void cvtx_kernel(const float* __restrict__ src, u16* __restrict__ hi,
                            u16* __restrict__ lo, int n4)
{
    int i = blockIdx.x * 256 + threadIdx.x;
    if (i >= n4) return;
    float4 v = *(const float4*)(src + (size_t)i * 4);
    u16 h0 = bfb(v.x), h1 = bfb(v.y), h2 = bfb(v.z), h3 = bfb(v.w);
    ushort4 hh = {h0, h1, h2, h3};
    ushort4 ll = {bfb(v.x - bff(h0)), bfb(v.y - bff(h1)), bfb(v.z - bff(h2)), bfb(v.w - bff(h3))};
    *(ushort4*)(hi + (size_t)i * 4) = hh;
    *(ushort4*)(lo + (size_t)i * 4) = ll;
}

__global__ void cvtw_kernel(const float* __restrict__ src, u16* __restrict__ hi,
                            u16* __restrict__ lo, int OC, int rows)
{
    int i = blockIdx.x * 256 + threadIdx.x;
    if (i >= rows * CC) return;
    int r = i / CC;
    float v = (r < OC) ? src[i] : 0.f;
    u16 h = bfb(v);
    hi[i] = h;
    lo[i] = bfb(v - bff(h));
}

// ---------------- pipelined bf16 hi/lo split GEMM ----------------
#define ASTR 40
#define BSTR 136
#define A_BUF_U (2 * 128 * ASTR)
#define B_BUF_U (2 * 32 * BSTR)
#define GEMM_SMEM ((2 * A_BUF_U + 2 * B_BUF_U) * 2)

__global__ void __launch_bounds__(256, 2)
mma_gemm2(const u16* __restrict__ Xh, const u16* __restrict__ Xl,
          const u16* __restrict__ Wh, const u16* __restrict__ Wl,
          const float* __restrict__ resid, float* __restrict__ Yf,
          u16* __restrict__ Yh, u16* __restrict__ Yl,
          int OC, int P)
{
    extern __shared__ u16 smu[];
    const uint32_t sbA = smem_u32(smu);
    const uint32_t sbB = sbA + 2 * A_BUF_U * 2;

    const int tid = threadIdx.x;
    const int warp = tid >> 5, lane = tid & 31;
    const int g4 = lane >> 2, t4 = lane & 3;
    const int wm = warp >> 1, wn = warp & 1;
    const int gz = blockIdx.z;
    const int oc0 = blockIdx.y * 128;
    const int p0 = blockIdx.x * 128;
    const size_t xoff = (size_t)gz * CC * P + p0;

    float acc[2][8][4];
#pragma unroll
    for (int mt = 0; mt < 2; mt++)
#pragma unroll
        for (int nt = 0; nt < 8; nt++)
#pragma unroll
            for (int e = 0; e < 4; e++) acc[mt][nt][e] = 0.f;

    auto prefetch = [&](int kc, int buf) {
        const int kbase = kc * 32;
        const uint32_t abase = sbA + buf * A_BUF_U * 2;
#pragma unroll
        for (int i = 0; i < 4; i++) {
            int op = tid + i * 256;
            int pl = op >> 9, rem = op & 511;
            int row = rem >> 2, cq = rem & 3;
            const u16* src = (pl ? Wl : Wh) + (size_t)(oc0 + row) * CC + kbase + cq * 8;
            uint32_t dst = abase + (uint32_t)((pl * 128 + row) * ASTR + cq * 8) * 2;
            cpa16(dst, src);
        }
        const uint32_t bbase = sbB + buf * B_BUF_U * 2;
#pragma unroll
        for (int i = 0; i < 4; i++) {
            int op = tid + i * 256;
            int pl = op >> 9, rem = op & 511;
            int row = rem >> 4, cq = rem & 15;
            const u16* src = (pl ? Xl : Xh) + xoff + (size_t)(kbase + row) * P + cq * 8;
            uint32_t dst = bbase + (uint32_t)((pl * 32 + row) * BSTR + cq * 8) * 2;
            cpa16(dst, src);
        }
    };

    prefetch(0, 0);
    CP_COMMIT();

    const int KC = CC / 32;
    for (int kc = 0; kc < KC; kc++) {
        if (kc + 1 < KC) {
            prefetch(kc + 1, (kc + 1) & 1);
            CP_COMMIT();
            CP_WAIT1();
        } else {
            CP_WAIT0();
        }
        __syncthreads();

        const int buf = kc & 1;
        const uint32_t aoff = sbA + buf * A_BUF_U * 2;
        const uint32_t boff = sbB + buf * B_BUF_U * 2;
#pragma unroll
        for (int ks = 0; ks < 2; ks++) {
            const int k0 = ks * 16;
            uint32_t ah[2][4], al[2][4];
#pragma unroll
            for (int mt = 0; mt < 2; mt++) {
                int mrow = wm * 32 + mt * 16 + (lane & 15);
                int kk = k0 + ((lane & 16) >> 1);
                ldsm4(ah[mt], aoff + (uint32_t)(mrow * ASTR + kk) * 2);
                ldsm4(al[mt], aoff + (uint32_t)((128 + mrow) * ASTR + kk) * 2);
            }
#pragma unroll
            for (int np = 0; np < 4; np++) {
                int krow = k0 + (lane & 15);
                int ncol = wn * 64 + np * 16 + ((lane & 16) >> 1);
                uint32_t bh[4], bl[4];
                ldsm4t(bh, boff + (uint32_t)(krow * BSTR + ncol) * 2);
                ldsm4t(bl, boff + (uint32_t)((32 + krow) * BSTR + ncol) * 2);
#pragma unroll
                for (int half = 0; half < 2; half++) {
                    int nt = np * 2 + half;
                    uint32_t* bhp = bh + half * 2;
                    uint32_t* blp = bl + half * 2;
                    mma16816(acc[0][nt], ah[0], bhp);
                    mma16816(acc[1][nt], ah[1], bhp);
                    mma16816(acc[0][nt], ah[0], blp);
                    mma16816(acc[1][nt], ah[1], blp);
                    mma16816(acc[0][nt], al[0], bhp);
                    mma16816(acc[1][nt], al[1], bhp);
                }
            }
        }
        __syncthreads();
    }

#pragma unroll
    for (int mt = 0; mt < 2; mt++) {
        int r0 = oc0 + wm * 32 + mt * 16 + g4;
#pragma unroll
        for (int nt = 0; nt < 8; nt++) {
            int p = p0 + wn * 64 + nt * 8 + t4 * 2;
#pragma unroll
            for (int hrow = 0; hrow < 2; hrow++) {
                int r = r0 + hrow * 8;
                if (r < OC) {
                    size_t o = ((size_t)gz * OC + r) * P + p;
                    float v0 = acc[mt][nt][hrow * 2 + 0];
                    float v1 = acc[mt][nt][hrow * 2 + 1];
                    if (resid) { v0 += resid[o]; v1 += resid[o + 1]; }
                    if (Yf) { Yf[o] = v0; Yf[o + 1] = v1; }
                    if (Yh) {
                        u16 h0 = bfb(v0), h1 = bfb(v1);
                        Yh[o] = h0; Yh[o + 1] = h1;
                        Yl[o] = bfb(v0 - bff(h0)); Yl[o + 1] = bfb(v1 - bff(h1));
                    }
                }
            }
        }
    }
}

// ---------------- depthwise 3x3 (4 px / thread) ----------------
__global__ void dw3v_kernel(const float* __restrict__ in, const float* __restrict__ w9,
                            float* __restrict__ out, int C, int Hn, int Wn, int total4)
{
    int idx = blockIdx.x * 256 + threadIdx.x;
    if (idx >= total4) return;
    int wq = Wn >> 2;
    int xg = (idx % wq) << 2;
    int t = idx / wq;
    int y = t % Hn;
    int c = (t / Hn) % C;
    const float* wp = w9 + c * 9;
    const float* rowc = in + (size_t)t * Wn;
    float a0 = 0.f, a1 = 0.f, a2 = 0.f, a3 = 0.f;
#pragma unroll
    for (int dy = -1; dy <= 1; dy++) {
        int yy = y + dy;
        if ((unsigned)yy >= (unsigned)Hn) continue;
        const float* r = rowc + (ptrdiff_t)dy * Wn;
        float4 v = *(const float4*)(r + xg);
        float left = (xg > 0) ? r[xg - 1] : 0.f;
        float right = (xg + 4 < Wn) ? r[xg + 4] : 0.f;
        float w0 = wp[(dy + 1) * 3], w1 = wp[(dy + 1) * 3 + 1], w2 = wp[(dy + 1) * 3 + 2];
        a0 += w0 * left + w1 * v.x + w2 * v.y;
        a1 += w0 * v.x + w1 * v.y + w2 * v.z;
        a2 += w0 * v.y + w1 * v.z + w2 * v.w;
        a3 += w0 * v.z + w1 * v.w + w2 * right;
    }
    *(float4*)(out + (size_t)t * Wn + xg) = make_float4(a0, a1, a2, a3);
}

// ---------------- level-0 row norms ----------------
__global__ void rownorm_kernel(const float* __restrict__ base, int chanPerBatch,
                               float* __restrict__ inv)
{
    int row = blockIdx.x;
    int b = row / CC, c = row % CC;
    const float* p = base + ((size_t)b * chanPerBatch + c) * HW;
    float s = 0.f;
    for (int i = threadIdx.x; i < HW; i += 256) { float v = p[i]; s += v * v; }
    __shared__ float red[256];
    red[threadIdx.x] = s;
    __syncthreads();
    for (int o = 128; o; o >>= 1) {
        if (threadIdx.x < o) red[threadIdx.x] += red[threadIdx.x + o];
        __syncthreads();
    }
    if (threadIdx.x == 0) inv[row] = 1.f / fmaxf(sqrtf(red[0]), 1e-12f);
}

// ---------------- level-0 S = q k^T ----------------
__global__ void s_accum_kernel(const float* __restrict__ q, const float* __restrict__ kv,
                               float* __restrict__ part)
{
    int bh = blockIdx.y;
    int b = bh / HEADS, h = bh % HEADS;
    const float* qb = q + ((size_t)b * CC + h * CHD) * HW;
    const float* kb = kv + ((size_t)b * 2 * CC + h * CHD) * HW;
    int n0 = blockIdx.x * 2048;
    __shared__ float qt[32][65], kt[32][65];
    float acc[4] = {0.f, 0.f, 0.f, 0.f};
    int tid = threadIdx.x;
    for (int ns = 0; ns < 2048; ns += 64) {
#pragma unroll
        for (int r = 0; r < 8; r++) {
            int e = tid + r * 256;
            int c = e >> 6, nn = e & 63;
            qt[c][nn] = qb[(size_t)c * HW + n0 + ns + nn];
            kt[c][nn] = kb[(size_t)c * HW + n0 + ns + nn];
        }
        __syncthreads();
#pragma unroll
        for (int i = 0; i < 4; i++) {
            int pr = i * 256 + tid;
            int c = pr >> 5, d = pr & 31;
            float a = 0.f;
#pragma unroll
            for (int kk = 0; kk < 64; kk++) a += qt[c][kk] * kt[d][kk];
            acc[i] += a;
        }
        __syncthreads();
    }
#pragma unroll
    for (int i = 0; i < 4; i++) {
        int pr = i * 256 + tid;
        part[((size_t)blockIdx.x * 24 + bh) * 1024 + pr] = acc[i];
    }
}

__global__ void s_reduce_kernel(const float* __restrict__ part, float* __restrict__ S)
{
    int idx = blockIdx.x * 256 + threadIdx.x;
    float s = 0.f;
    for (int ck = 0; ck < 32; ck++) s += part[(size_t)ck * 24576 + idx];
    S[idx] = s;
}

// ---------------- level-0 softmax ----------------
__global__ void softmax0_kernel(const float* __restrict__ S, const float* __restrict__ invq,
                                const float* __restrict__ invk, const float* __restrict__ temp0,
                                float* __restrict__ A)
{
    int bh = blockIdx.x;
    int b = bh / HEADS, h = bh % HEADS;
    int c = threadIdx.y, d = threadIdx.x;
    float v = S[bh * 1024 + c * 32 + d] * invq[b * CC + h * CHD + c] *
              invk[b * CC + h * CHD + d] * temp0[h];
    float m = v;
#pragma unroll
    for (int o = 16; o; o >>= 1) m = fmaxf(m, __shfl_xor_sync(0xffffffffu, m, o));
    float e = expf(v - m);
    float s = e;
#pragma unroll
    for (int o = 16; o; o >>= 1) s += __shfl_xor_sync(0xffffffffu, s, o);
    A[bh * 1024 + c * 32 + d] = e / s;
}

// ---------------- level-0 out = A @ v -> bf16 planes ----------------
__global__ void out0n_kernel(const float* __restrict__ A, const float* __restrict__ kv,
                             u16* __restrict__ oh, u16* __restrict__ ol)
{
    int bh = blockIdx.y;
    int b = bh / HEADS, h = bh % HEADS;
    __shared__ float As[32][33];
    int tid = threadIdx.x;
    for (int e = tid; e < 1024; e += 256) As[e >> 5][e & 31] = A[bh * 1024 + e];
    __syncthreads();
    int n = blockIdx.x * 256 + tid;
    const float* vb = kv + ((size_t)b * 2 * CC + CC + h * CHD) * HW + n;
    float vr[32];
#pragma unroll
    for (int d = 0; d < 32; d++) vr[d] = vb[(size_t)d * HW];
    size_t ob = ((size_t)b * CC + h * CHD) * HW + n;
#pragma unroll
    for (int c = 0; c < 32; c++) {
        float s = 0.f;
#pragma unroll
        for (int d = 0; d < 32; d++) s += As[c][d] * vr[d];
        u16 hv = bfb(s);
        oh[ob + (size_t)c * HW] = hv;
        ol[ob + (size_t)c * HW] = bfb(s - bff(hv));
    }
}

// ---------------- avg pool 2x2 (fp32 + planes) ----------------
__global__ void avgpool_kernel(const float* __restrict__ x, float* __restrict__ o,
                               u16* __restrict__ oh, u16* __restrict__ ol)
{
    int idx = blockIdx.x * 256 + threadIdx.x;
    if (idx >= HB * CC * HW2) return;
    int xx = idx & 127;
    int yy = (idx >> 7) & 127;
    int bc = idx >> 14;
    const float* p = x + (size_t)bc * HW + (yy * 2) * 256 + xx * 2;
    float v = 0.25f * (p[0] + p[1] + p[256] + p[257]);
    o[idx] = v;
    u16 h = bfb(v);
    oh[idx] = h;
    ol[idx] = bfb(v - bff(h));
}

// ---------------- q1 regrouping gather ----------------
__global__ void q1gather_kernel(const float* __restrict__ qt, float* __restrict__ qr)
{
    int idx = blockIdx.x * 256 + threadIdx.x;
    if (idx >= 16 * CC * HW2) return;
    int x = idx & 127;
    int y = (idx >> 7) & 127;
    int c = (idx >> 14) % CC;
    int img = idx / (CC * HW2);
    int whp = y >> 3, yy = y & 7, wwp = x >> 3, xx = x & 7;
    int k = img & 3, b = img >> 2;
    int wh = 8 * k + (whp >> 1);
    int ww = ((whp & 1) << 4) + wwp;
    int sy = wh * 8 + yy, sx = ww * 8 + xx;
    qr[idx] = qt[((size_t)b * CC + c) * HW + sy * 256 + sx];
}

// ---------------- shifted-window cosine attention (register-tiled) ----------------
#define ATS 76
__global__ void winattn_kernel(const float* __restrict__ qg, const float* __restrict__ kvg,
                               const float* __restrict__ rpbt, const float* __restrict__ temp1,
                               u16* __restrict__ oh, u16* __restrict__ ol)
{
    extern __shared__ float smw[];
    float* qs = smw;                  // 192*64
    float* ks = qs + 192 * 64;        // 192*64
    float* vs = ks + 192 * 64;        // 192*64
    float* at = vs + 192 * 64;        // 64*ATS
    float* inq = at + 64 * ATS;       // 384
    float* ink = inq + 384;           // 384

    int win = blockIdx.x;
    int img = win >> 8;
    int loc = win & 255;
    int whp = loc >> 4, wwp = loc & 15;
    int kwin = win >> 2;
    int bk = kwin >> 8;
    int loc2 = kwin & 255;
    int gh = loc2 >> 4, gw = loc2 & 15;
    int tid = threadIdx.x;

    for (int e = tid; e < 192 * 64; e += 256) {
        int c = e >> 6, t = e & 63;
        int yy = t >> 3, xx = t & 7;
        int y = (whp * 8 + yy + 4) & 127;
        int x = (wwp * 8 + xx + 4) & 127;
        qs[e] = qg[((size_t)img * CC + c) * HW2 + y * 128 + x];
    }
    for (int e = tid; e < 192 * 64; e += 256) {
        int c = e >> 6, t = e & 63;
        int yy = t >> 3, xx = t & 7;
        int y = (gh * 8 + yy + 4) & 127;
        int x = (gw * 8 + xx + 4) & 127;
        size_t base = ((size_t)bk * 2 * CC + c) * HW2 + y * 128 + x;
        ks[e] = kvg[base];
        vs[e] = kvg[base + (size_t)CC * HW2];
    }
    __syncthreads();

    for (int e = tid; e < 384; e += 256) {
        int h = e >> 6, t = e & 63;
        float sq = 0.f, sk = 0.f;
#pragma unroll
        for (int i = 0; i < 32; i++) {
            float a = qs[(h * 32 + i) * 64 + t]; sq += a * a;
            float b = ks[(h * 32 + i) * 64 + t]; sk += b * b;
        }
        inq[e] = 1.f / fmaxf(sqrtf(sq), 1e-12f);
        ink[e] = 1.f / fmaxf(sqrtf(sk), 1e-12f);
    }
    __syncthreads();

    // precompute region labels for tokens 0..63 (depends only on gh/gw)
    int labn[4];   // per 4 tokens handled via recompute; cheap inline instead
    (void)labn;

    const int ng = tid >> 4, mg = tid & 15;       // logits tile ids
    const int n0L = ng * 4, m0L = mg * 4;
    const int igA = tid >> 5, ngA = tid & 31;     // AV tile ids
    const int i0A = igA * 4, n0A = ngA * 2;

    for (int h = 0; h < HEADS; h++) {
        float tmp = temp1[h];
        // ---- logits: 4n x 4m per thread, float4 smem reads ----
        {
            float a[4][4];
#pragma unroll
            for (int r = 0; r < 4; r++)
#pragma unroll
                for (int c = 0; c < 4; c++) a[r][c] = 0.f;
            const float* qp = qs + (h * 32) * 64 + n0L;
            const float* kp = ks + (h * 32) * 64 + m0L;
#pragma unroll
            for (int i = 0; i < 32; i++) {
                float4 qv = *(const float4*)(qp + i * 64);
                float4 kv4 = *(const float4*)(kp + i * 64);
                float qa[4] = {qv.x, qv.y, qv.z, qv.w};
                float ka[4] = {kv4.x, kv4.y, kv4.z, kv4.w};
#pragma unroll
                for (int r = 0; r < 4; r++)
#pragma unroll
                    for (int c = 0; c < 4; c++) a[r][c] = fmaf(qa[r], ka[c], a[r][c]);
            }
#pragma unroll
            for (int r = 0; r < 4; r++) {
                int n = n0L + r;
                int yn = n >> 3, xn = n & 7;
                int pyn = gh * 8 + yn, pxn = gw * 8 + xn;
                int ln = (pyn < 120 ? 0 : (pyn < 124 ? 1 : 2)) * 3 + (pxn < 120 ? 0 : (pxn < 124 ? 1 : 2));
                float qn = inq[h * 64 + n] * tmp;
                float4 row;
                float* rp = (float*)&row;
#pragma unroll
                for (int c = 0; c < 4; c++) {
                    int m = m0L + c;
                    int ym = m >> 3, xm = m & 7;
                    float s = a[r][c] * qn * ink[h * 64 + m];
                    int ridx = (yn - ym + 7) * 15 + (xn - xm + 7);
                    s += rpbt[ridx * HEADS + h];
                    int pym = gh * 8 + ym, pxm = gw * 8 + xm;
                    int lm = (pym < 120 ? 0 : (pym < 124 ? 1 : 2)) * 3 + (pxm < 120 ? 0 : (pxm < 124 ? 1 : 2));
                    if (ln != lm) s -= 100.f;
                    rp[c] = s;
                }
                *(float4*)(at + n * ATS + m0L) = row;
            }
        }
        __syncthreads();
        // ---- row softmax (8 warps, 8 rows each) with FMA-pipe exp ----
        {
            int wid = tid >> 5, lane = tid & 31;
            for (int r = wid; r < 64; r += 8) {
                float v0 = at[r * ATS + lane], v1 = at[r * ATS + lane + 32];
                float mx = fmaxf(v0, v1);
#pragma unroll
                for (int o = 16; o; o >>= 1) mx = fmaxf(mx, __shfl_xor_sync(0xffffffffu, mx, o));
                v0 = fexp(v0 - mx);
                v1 = fexp(v1 - mx);
                float su = v0 + v1;
#pragma unroll
                for (int o = 16; o; o >>= 1) su += __shfl_xor_sync(0xffffffffu, su, o);
                float inv = 1.f / su;
                at[r * ATS + lane] = v0 * inv;
                at[r * ATS + lane + 32] = v1 * inv;
            }
        }
        __syncthreads();
        // ---- AV: 4i x 2n per thread, float4 smem reads; direct global writes ----
        {
            float o2[4][2];
#pragma unroll
            for (int j = 0; j < 4; j++) { o2[j][0] = 0.f; o2[j][1] = 0.f; }
            const float* vbase = vs + (h * 32 + i0A) * 64;
            const float* abase = at + n0A * ATS;
#pragma unroll
            for (int m4 = 0; m4 < 16; m4++) {
                int m = m4 * 4;
                float4 a0 = *(const float4*)(abase + m);
                float4 a1 = *(const float4*)(abase + ATS + m);
#pragma unroll
                for (int j = 0; j < 4; j++) {
                    float4 vv = *(const float4*)(vbase + j * 64 + m);
                    o2[j][0] += vv.x * a0.x + vv.y * a0.y + vv.z * a0.z + vv.w * a0.w;
                    o2[j][1] += vv.x * a1.x + vv.y * a1.y + vv.z * a1.z + vv.w * a1.w;
                }
            }
#pragma unroll
            for (int j = 0; j < 4; j++) {
                int c = h * 32 + i0A + j;
                size_t o = (size_t)c * 262144 + (size_t)win * 64 + n0A;
                float v0 = o2[j][0], v1 = o2[j][1];
                u16 h0 = bfb(v0), h1 = bfb(v1);
                oh[o] = h0; oh[o + 1] = h1;
                ol[o] = bfb(v0 - bff(h0)); ol[o + 1] = bfb(v1 - bff(h1));
            }
        }
        __syncthreads();
    }
}

// ---------------- proj1 result scatter-add ----------------
__global__ void scatter1_kernel(const float* __restrict__ pin, float* __restrict__ out)
{
    int idx = blockIdx.x * 256 + threadIdx.x;
    if (idx >= CC * 262144) return;
    int p = idx & 262143;
    int cc = idx >> 18;
    int w = p >> 6;
    int t = p & 63;
    int yy = t >> 3, xx = t & 7;
    int b = w >> 10;
    int wh = (w >> 5) & 31;
    int wn = w & 31;
    int y = (wh * 8 + yy + 4) & 255;
    int x = (wn * 8 + xx + 4) & 255;
    out[((size_t)b * CC + cc) * HW + y * 256 + x] += pin[idx];
}

// ==================================================================
extern "C" void kernel_launch(void* const* d_in, const int* in_sizes, int n_in,
                              void* d_out, int out_size)
{
    const float* x      = (const float*)d_in[0];
    const float* Wq0    = (const float*)d_in[1];
    const float* Wqdw0  = (const float*)d_in[2];
    const float* Wkv0   = (const float*)d_in[3];
    const float* Wkvdw0 = (const float*)d_in[4];
    const float* Wq1    = (const float*)d_in[5];
    const float* Wqdw1  = (const float*)d_in[6];
    const float* Wkv1   = (const float*)d_in[7];
    const float* Wkvdw1 = (const float*)d_in[8];
    const float* Wproj0 = (const float*)d_in[9];
    const float* Wproj1 = (const float*)d_in[10];
    const float* temp0  = (const float*)d_in[11];
    const float* temp1  = (const float*)d_in[12];
    const float* rpbt   = (const float*)d_in[13];
    const float* Wds    = (const float*)d_in[14];
    float* out = (float*)d_out;

    float *A, *B, *invq, *invk, *Sb, *A0, *part;
    u16 *Xh, *Xl, *Wh, *Wl;
    cudaGetSymbolAddress((void**)&A, g_A);
    cudaGetSymbolAddress((void**)&B, g_B);
    cudaGetSymbolAddress((void**)&Xh, g_Xh);
    cudaGetSymbolAddress((void**)&Xl, g_Xl);
    cudaGetSymbolAddress((void**)&Wh, g_Wh);
    cudaGetSymbolAddress((void**)&Wl, g_Wl);
    cudaGetSymbolAddress((void**)&invq, g_invq);
    cudaGetSymbolAddress((void**)&invk, g_invk);
    cudaGetSymbolAddress((void**)&Sb, g_S);
    cudaGetSymbolAddress((void**)&A0, g_A0);
    cudaGetSymbolAddress((void**)&part, g_part);

    const size_t OFF50 = 50331648;
    float* A2 = A + OFF50;

    float* poolF = B;
    u16* poolH = (u16*)(B + 12582912);
    u16* poolL = (u16*)(B + 12582912 + 6291456);
    u16* xdsH  = (u16*)(B + 25165824);
    u16* xdsL  = (u16*)(B + 31457280);
    float* kv1t = B + 37748736;
    float* kv1  = B + 62914560;
    u16* P0h = (u16*)A;
    u16* P0l = (u16*)(A + 25165824);
    u16* W1h = (u16*)B;
    u16* W1l = (u16*)(B + 25165824);

    cudaFuncSetAttribute(mma_gemm2, cudaFuncAttributeMaxDynamicSharedMemorySize, GEMM_SMEM);

    // ---- conversions ----
    cvtw_kernel<<<(256 * CC + 255) / 256, 256>>>(Wq0,    Wh + WO_Q0,  Wl + WO_Q0,  192, 256);
    cvtw_kernel<<<(384 * CC + 255) / 256, 256>>>(Wkv0,   Wh + WO_KV0, Wl + WO_KV0, 384, 384);
    cvtw_kernel<<<(256 * CC + 255) / 256, 256>>>(Wq1,    Wh + WO_Q1,  Wl + WO_Q1,  192, 256);
    cvtw_kernel<<<(384 * CC + 255) / 256, 256>>>(Wkv1,   Wh + WO_KV1, Wl + WO_KV1, 384, 384);
    cvtw_kernel<<<(256 * CC + 255) / 256, 256>>>(Wproj0, Wh + WO_P0,  Wl + WO_P0,  192, 256);
    cvtw_kernel<<<(256 * CC + 255) / 256, 256>>>(Wproj1, Wh + WO_P1,  Wl + WO_P1,  192, 256);
    cvtw_kernel<<<(256 * CC + 255) / 256, 256>>>(Wds,    Wh + WO_DS,  Wl + WO_DS,  192, 256);
    cvtx_kernel<<<49152, 256>>>(x, Xh, Xl, 12582912);

    // ---------- level 0 ----------
    mma_gemm2<<<dim3(512, 3, 4), 256, GEMM_SMEM>>>(Xh, Xl, Wh + WO_KV0, Wl + WO_KV0,
                                                   nullptr, A, nullptr, nullptr, 2 * CC, HW);
    dw3v_kernel<<<(4 * 2 * CC * HW / 4) / 256, 256>>>(A, Wkvdw0, B, 2 * CC, 256, 256, 4 * 2 * CC * HW / 4);
    mma_gemm2<<<dim3(512, 2, 4), 256, GEMM_SMEM>>>(Xh, Xl, Wh + WO_Q0, Wl + WO_Q0,
                                                   nullptr, A, nullptr, nullptr, CC, HW);
    dw3v_kernel<<<(4 * CC * HW / 4) / 256, 256>>>(A, Wqdw0, A2, CC, 256, 256, 4 * CC * HW / 4);
    rownorm_kernel<<<768, 256>>>(A2, CC, invq);
    rownorm_kernel<<<768, 256>>>(B, 2 * CC, invk);
    s_accum_kernel<<<dim3(32, 24), 256>>>(A2, B, part);
    s_reduce_kernel<<<96, 256>>>(part, Sb);
    softmax0_kernel<<<24, dim3(32, 32)>>>(Sb, invq, invk, temp0, A0);
    out0n_kernel<<<dim3(256, 24), 256>>>(A0, B, P0h, P0l);
    mma_gemm2<<<dim3(512, 2, 4), 256, GEMM_SMEM>>>(P0h, P0l, Wh + WO_P0, Wl + WO_P0,
                                                   nullptr, out, nullptr, nullptr, CC, HW);

    // ---------- level 1 ----------
    avgpool_kernel<<<(4 * CC * HW2) / 256, 256>>>(x, poolF, poolH, poolL);
    mma_gemm2<<<dim3(128, 2, 4), 256, GEMM_SMEM>>>(poolH, poolL, Wh + WO_DS, Wl + WO_DS,
                                                   poolF, nullptr, xdsH, xdsL, CC, HW2);
    mma_gemm2<<<dim3(128, 3, 4), 256, GEMM_SMEM>>>(xdsH, xdsL, Wh + WO_KV1, Wl + WO_KV1,
                                                   nullptr, kv1t, nullptr, nullptr, 2 * CC, HW2);
    dw3v_kernel<<<(4 * 2 * CC * HW2 / 4) / 256, 256>>>(kv1t, Wkvdw1, kv1, 2 * CC, 128, 128, 4 * 2 * CC * HW2 / 4);
    mma_gemm2<<<dim3(512, 2, 4), 256, GEMM_SMEM>>>(Xh, Xl, Wh + WO_Q1, Wl + WO_Q1,
                                                   nullptr, A, nullptr, nullptr, CC, HW);
    q1gather_kernel<<<(16 * CC * HW2) / 256, 256>>>(A, A2);
    dw3v_kernel<<<(16 * CC * HW2 / 4) / 256, 256>>>(A2, Wqdw1, A, CC, 128, 128, 16 * CC * HW2 / 4);
    {
        int smemBytes = (3 * 192 * 64 + 64 * ATS + 2 * 384) * 4;
        cudaFuncSetAttribute(winattn_kernel, cudaFuncAttributeMaxDynamicSharedMemorySize, smemBytes);
        winattn_kernel<<<4096, 256, smemBytes>>>(A, kv1, rpbt, temp1, W1h, W1l);
    }
    mma_gemm2<<<dim3(2048, 2, 1), 256, GEMM_SMEM>>>(W1h, W1l, Wh + WO_P1, Wl + WO_P1,
                                                    nullptr, A2, nullptr, nullptr, CC, 262144);
    scatter1_kernel<<<(CC * 262144) / 256, 256>>>(A2, out);
}

// round 8
// speedup vs baseline: 1.5227x; 1.5227x over previous
#include <cuda_runtime.h>
#include <cuda_bf16.h>
#include <math.h>
#include <stdint.h>

#define HB 4
#define CC 192
#define HW 65536
#define HW2 16384
#define HEADS 6
#define CHD 32

typedef unsigned short u16;

// ---------------- static scratch ----------------
__device__ float g_A[100663296];      // 402 MB
__device__ float g_B[100663296];      // 402 MB
__device__ u16   g_Xh[50331648];      // x bf16 hi plane
__device__ u16   g_Xl[50331648];      // x bf16 lo plane
__device__ u16   g_Wh[393216];
__device__ u16   g_Wl[393216];
__device__ float g_invq[768];
__device__ float g_invk[768];
__device__ float g_S[24 * 1024];
__device__ float g_A0[24 * 1024];
__device__ float g_part[32 * 24 * 1024];

#define WO_Q0    0
#define WO_KV0   49152
#define WO_Q1    122880
#define WO_KV1   172032
#define WO_P0    245760
#define WO_P1    294912
#define WO_DS    344064

// ================= helpers =================
__device__ __forceinline__ u16 bfb(float v) {
    __nv_bfloat16 b = __float2bfloat16(v);
    return *(u16*)&b;
}
__device__ __forceinline__ float bff(u16 s) {
    __nv_bfloat16 b = *(__nv_bfloat16*)&s;
    return __bfloat162float(b);
}
__device__ __forceinline__ uint32_t smem_u32(const void* p) {
    uint32_t a;
    asm("{ .reg .u64 t; cvta.to.shared.u64 t, %1; cvt.u32.u64 %0, t; }" : "=r"(a) : "l"(p));
    return a;
}
__device__ __forceinline__ void mma16816(float* d, const uint32_t* a, const uint32_t* b) {
    asm volatile(
        "mma.sync.aligned.m16n8k16.row.col.f32.bf16.bf16.f32 "
        "{%0,%1,%2,%3}, {%4,%5,%6,%7}, {%8,%9}, {%0,%1,%2,%3};"
        : "+f"(d[0]), "+f"(d[1]), "+f"(d[2]), "+f"(d[3])
        : "r"(a[0]), "r"(a[1]), "r"(a[2]), "r"(a[3]), "r"(b[0]), "r"(b[1]));
}
__device__ __forceinline__ void ldsm4(uint32_t* r, uint32_t addr) {
    asm volatile("ldmatrix.sync.aligned.m8n8.x4.shared.b16 {%0,%1,%2,%3}, [%4];"
        : "=r"(r[0]), "=r"(r[1]), "=r"(r[2]), "=r"(r[3]) : "r"(addr));
}
__device__ __forceinline__ void ldsm4t(uint32_t* r, uint32_t addr) {
    asm volatile("ldmatrix.sync.aligned.m8n8.x4.trans.shared.b16 {%0,%1,%2,%3}, [%4];"
        : "=r"(r[0]), "=r"(r[1]), "=r"(r[2]), "=r"(r[3]) : "r"(addr));
}
__device__ __forceinline__ void cpa16(uint32_t dst, const void* src) {
    asm volatile("cp.async.cg.shared.global [%0], [%1], 16;" :: "r"(dst), "l"(src));
}
#define CP_COMMIT() asm volatile("cp.async.commit_group;" ::: "memory")
#define CP_WAIT0()  asm volatile("cp.async.wait_group 0;" ::: "memory")
#define CP_WAIT1()  asm volatile("cp.async.wait_group 1;" ::: "memory")

// fast exp on FMA pipe (inputs <= 0 after max subtraction; mask makes them >= -150)
__device__ __forceinline__ float fexp(float x) {
    float t = x * 1.44269504089f;
    t = fmaxf(t, -126.f);
    float fi = rintf(t);
    float f = t - fi;
    float p = 0.00015403530393f;
    p = fmaf(p, f, 0.00133335581464f);
    p = fmaf(p, f, 0.00961812910763f);
    p = fmaf(p, f, 0.05550410866482f);
    p = fmaf(p, f, 0.24022650695910f);
    p = fmaf(p, f, 0.69314718055995f);
    p = fmaf(p, f, 1.0f);
    int i = (int)fi;
    float s = __int_as_float((i + 127) << 23);
    return p * s;
}

// ---------------- conversion kernels ----------------
__global__ void cvtx_kernel(const float* __restrict__ src, u16* __restrict__ hi,
                            u16* __restrict__ lo, int n4)
{
    int i = blockIdx.x * 256 + threadIdx.x;
    if (i >= n4) return;
    float4 v = *(const float4*)(src + (size_t)i * 4);
    u16 h0 = bfb(v.x), h1 = bfb(v.y), h2 = bfb(v.z), h3 = bfb(v.w);
    ushort4 hh = {h0, h1, h2, h3};
    ushort4 ll = {bfb(v.x - bff(h0)), bfb(v.y - bff(h1)), bfb(v.z - bff(h2)), bfb(v.w - bff(h3))};
    *(ushort4*)(hi + (size_t)i * 4) = hh;
    *(ushort4*)(lo + (size_t)i * 4) = ll;
}

__global__ void cvtw_kernel(const float* __restrict__ src, u16* __restrict__ hi,
                            u16* __restrict__ lo, int OC, int rows)
{
    int i = blockIdx.x * 256 + threadIdx.x;
    if (i >= rows * CC) return;
    int r = i / CC;
    float v = (r < OC) ? src[i] : 0.f;
    u16 h = bfb(v);
    hi[i] = h;
    lo[i] = bfb(v - bff(h));
}

// ---------------- pipelined bf16 hi/lo split GEMM ----------------
#define ASTR 40
#define BSTR 136
#define A_BUF_U (2 * 128 * ASTR)
#define B_BUF_U (2 * 32 * BSTR)
#define GEMM_SMEM ((2 * A_BUF_U + 2 * B_BUF_U) * 2)

__global__ void __launch_bounds__(256, 2)
mma_gemm2(const u16* __restrict__ Xh, const u16* __restrict__ Xl,
          const u16* __restrict__ Wh, const u16* __restrict__ Wl,
          const float* __restrict__ resid, float* __restrict__ Yf,
          u16* __restrict__ Yh, u16* __restrict__ Yl,
          int OC, int P)
{
    extern __shared__ u16 smu[];
    const uint32_t sbA = smem_u32(smu);
    const uint32_t sbB = sbA + 2 * A_BUF_U * 2;

    const int tid = threadIdx.x;
    const int warp = tid >> 5, lane = tid & 31;
    const int g4 = lane >> 2, t4 = lane & 3;
    const int wm = warp >> 1, wn = warp & 1;
    const int gz = blockIdx.z;
    const int oc0 = blockIdx.y * 128;
    const int p0 = blockIdx.x * 128;
    const size_t xoff = (size_t)gz * CC * P + p0;

    float acc[2][8][4];
#pragma unroll
    for (int mt = 0; mt < 2; mt++)
#pragma unroll
        for (int nt = 0; nt < 8; nt++)
#pragma unroll
            for (int e = 0; e < 4; e++) acc[mt][nt][e] = 0.f;

    auto prefetch = [&](int kc, int buf) {
        const int kbase = kc * 32;
        const uint32_t abase = sbA + buf * A_BUF_U * 2;
#pragma unroll
        for (int i = 0; i < 4; i++) {
            int op = tid + i * 256;
            int pl = op >> 9, rem = op & 511;
            int row = rem >> 2, cq = rem & 3;
            const u16* src = (pl ? Wl : Wh) + (size_t)(oc0 + row) * CC + kbase + cq * 8;
            uint32_t dst = abase + (uint32_t)((pl * 128 + row) * ASTR + cq * 8) * 2;
            cpa16(dst, src);
        }
        const uint32_t bbase = sbB + buf * B_BUF_U * 2;
#pragma unroll
        for (int i = 0; i < 4; i++) {
            int op = tid + i * 256;
            int pl = op >> 9, rem = op & 511;
            int row = rem >> 4, cq = rem & 15;
            const u16* src = (pl ? Xl : Xh) + xoff + (size_t)(kbase + row) * P + cq * 8;
            uint32_t dst = bbase + (uint32_t)((pl * 32 + row) * BSTR + cq * 8) * 2;
            cpa16(dst, src);
        }
    };

    prefetch(0, 0);
    CP_COMMIT();

    const int KC = CC / 32;
    for (int kc = 0; kc < KC; kc++) {
        if (kc + 1 < KC) {
            prefetch(kc + 1, (kc + 1) & 1);
            CP_COMMIT();
            CP_WAIT1();
        } else {
            CP_WAIT0();
        }
        __syncthreads();

        const int buf = kc & 1;
        const uint32_t aoff = sbA + buf * A_BUF_U * 2;
        const uint32_t boff = sbB + buf * B_BUF_U * 2;
#pragma unroll
        for (int ks = 0; ks < 2; ks++) {
            const int k0 = ks * 16;
            uint32_t ah[2][4], al[2][4];
#pragma unroll
            for (int mt = 0; mt < 2; mt++) {
                int mrow = wm * 32 + mt * 16 + (lane & 15);
                int kk = k0 + ((lane & 16) >> 1);
                ldsm4(ah[mt], aoff + (uint32_t)(mrow * ASTR + kk) * 2);
                ldsm4(al[mt], aoff + (uint32_t)((128 + mrow) * ASTR + kk) * 2);
            }
#pragma unroll
            for (int np = 0; np < 4; np++) {
                int krow = k0 + (lane & 15);
                int ncol = wn * 64 + np * 16 + ((lane & 16) >> 1);
                uint32_t bh[4], bl[4];
                ldsm4t(bh, boff + (uint32_t)(krow * BSTR + ncol) * 2);
                ldsm4t(bl, boff + (uint32_t)((32 + krow) * BSTR + ncol) * 2);
#pragma unroll
                for (int half = 0; half < 2; half++) {
                    int nt = np * 2 + half;
                    uint32_t* bhp = bh + half * 2;
                    uint32_t* blp = bl + half * 2;
                    mma16816(acc[0][nt], ah[0], bhp);
                    mma16816(acc[1][nt], ah[1], bhp);
                    mma16816(acc[0][nt], ah[0], blp);
                    mma16816(acc[1][nt], ah[1], blp);
                    mma16816(acc[0][nt], al[0], bhp);
                    mma16816(acc[1][nt], al[1], bhp);
                }
            }
        }
        __syncthreads();
    }

#pragma unroll
    for (int mt = 0; mt < 2; mt++) {
        int r0 = oc0 + wm * 32 + mt * 16 + g4;
#pragma unroll
        for (int nt = 0; nt < 8; nt++) {
            int p = p0 + wn * 64 + nt * 8 + t4 * 2;
#pragma unroll
            for (int hrow = 0; hrow < 2; hrow++) {
                int r = r0 + hrow * 8;
                if (r < OC) {
                    size_t o = ((size_t)gz * OC + r) * P + p;
                    float v0 = acc[mt][nt][hrow * 2 + 0];
                    float v1 = acc[mt][nt][hrow * 2 + 1];
                    if (resid) { v0 += resid[o]; v1 += resid[o + 1]; }
                    if (Yf) { Yf[o] = v0; Yf[o + 1] = v1; }
                    if (Yh) {
                        u16 h0 = bfb(v0), h1 = bfb(v1);
                        Yh[o] = h0; Yh[o + 1] = h1;
                        Yl[o] = bfb(v0 - bff(h0)); Yl[o + 1] = bfb(v1 - bff(h1));
                    }
                }
            }
        }
    }
}

// ---------------- depthwise 3x3 (4 px / thread) ----------------
__global__ void dw3v_kernel(const float* __restrict__ in, const float* __restrict__ w9,
                            float* __restrict__ out, int C, int Hn, int Wn, int total4)
{
    int idx = blockIdx.x * 256 + threadIdx.x;
    if (idx >= total4) return;
    int wq = Wn >> 2;
    int xg = (idx % wq) << 2;
    int t = idx / wq;
    int y = t % Hn;
    int c = (t / Hn) % C;
    const float* wp = w9 + c * 9;
    const float* rowc = in + (size_t)t * Wn;
    float a0 = 0.f, a1 = 0.f, a2 = 0.f, a3 = 0.f;
#pragma unroll
    for (int dy = -1; dy <= 1; dy++) {
        int yy = y + dy;
        if ((unsigned)yy >= (unsigned)Hn) continue;
        const float* r = rowc + (ptrdiff_t)dy * Wn;
        float4 v = *(const float4*)(r + xg);
        float left = (xg > 0) ? r[xg - 1] : 0.f;
        float right = (xg + 4 < Wn) ? r[xg + 4] : 0.f;
        float w0 = wp[(dy + 1) * 3], w1 = wp[(dy + 1) * 3 + 1], w2 = wp[(dy + 1) * 3 + 2];
        a0 += w0 * left + w1 * v.x + w2 * v.y;
        a1 += w0 * v.x + w1 * v.y + w2 * v.z;
        a2 += w0 * v.y + w1 * v.z + w2 * v.w;
        a3 += w0 * v.z + w1 * v.w + w2 * right;
    }
    *(float4*)(out + (size_t)t * Wn + xg) = make_float4(a0, a1, a2, a3);
}

// ---------------- level-0 row norms ----------------
__global__ void rownorm_kernel(const float* __restrict__ base, int chanPerBatch,
                               float* __restrict__ inv)
{
    int row = blockIdx.x;
    int b = row / CC, c = row % CC;
    const float* p = base + ((size_t)b * chanPerBatch + c) * HW;
    float s = 0.f;
    for (int i = threadIdx.x; i < HW; i += 256) { float v = p[i]; s += v * v; }
    __shared__ float red[256];
    red[threadIdx.x] = s;
    __syncthreads();
    for (int o = 128; o; o >>= 1) {
        if (threadIdx.x < o) red[threadIdx.x] += red[threadIdx.x + o];
        __syncthreads();
    }
    if (threadIdx.x == 0) inv[row] = 1.f / fmaxf(sqrtf(red[0]), 1e-12f);
}

// ---------------- level-0 S = q k^T ----------------
__global__ void s_accum_kernel(const float* __restrict__ q, const float* __restrict__ kv,
                               float* __restrict__ part)
{
    int bh = blockIdx.y;
    int b = bh / HEADS, h = bh % HEADS;
    const float* qb = q + ((size_t)b * CC + h * CHD) * HW;
    const float* kb = kv + ((size_t)b * 2 * CC + h * CHD) * HW;
    int n0 = blockIdx.x * 2048;
    __shared__ float qt[32][65], kt[32][65];
    float acc[4] = {0.f, 0.f, 0.f, 0.f};
    int tid = threadIdx.x;
    for (int ns = 0; ns < 2048; ns += 64) {
#pragma unroll
        for (int r = 0; r < 8; r++) {
            int e = tid + r * 256;
            int c = e >> 6, nn = e & 63;
            qt[c][nn] = qb[(size_t)c * HW + n0 + ns + nn];
            kt[c][nn] = kb[(size_t)c * HW + n0 + ns + nn];
        }
        __syncthreads();
#pragma unroll
        for (int i = 0; i < 4; i++) {
            int pr = i * 256 + tid;
            int c = pr >> 5, d = pr & 31;
            float a = 0.f;
#pragma unroll
            for (int kk = 0; kk < 64; kk++) a += qt[c][kk] * kt[d][kk];
            acc[i] += a;
        }
        __syncthreads();
    }
#pragma unroll
    for (int i = 0; i < 4; i++) {
        int pr = i * 256 + tid;
        part[((size_t)blockIdx.x * 24 + bh) * 1024 + pr] = acc[i];
    }
}

__global__ void s_reduce_kernel(const float* __restrict__ part, float* __restrict__ S)
{
    int idx = blockIdx.x * 256 + threadIdx.x;
    float s = 0.f;
    for (int ck = 0; ck < 32; ck++) s += part[(size_t)ck * 24576 + idx];
    S[idx] = s;
}

// ---------------- level-0 softmax ----------------
__global__ void softmax0_kernel(const float* __restrict__ S, const float* __restrict__ invq,
                                const float* __restrict__ invk, const float* __restrict__ temp0,
                                float* __restrict__ A)
{
    int bh = blockIdx.x;
    int b = bh / HEADS, h = bh % HEADS;
    int c = threadIdx.y, d = threadIdx.x;
    float v = S[bh * 1024 + c * 32 + d] * invq[b * CC + h * CHD + c] *
              invk[b * CC + h * CHD + d] * temp0[h];
    float m = v;
#pragma unroll
    for (int o = 16; o; o >>= 1) m = fmaxf(m, __shfl_xor_sync(0xffffffffu, m, o));
    float e = expf(v - m);
    float s = e;
#pragma unroll
    for (int o = 16; o; o >>= 1) s += __shfl_xor_sync(0xffffffffu, s, o);
    A[bh * 1024 + c * 32 + d] = e / s;
}

// ---------------- level-0 out = A @ v -> bf16 planes ----------------
__global__ void out0n_kernel(const float* __restrict__ A, const float* __restrict__ kv,
                             u16* __restrict__ oh, u16* __restrict__ ol)
{
    int bh = blockIdx.y;
    int b = bh / HEADS, h = bh % HEADS;
    __shared__ float As[32][33];
    int tid = threadIdx.x;
    for (int e = tid; e < 1024; e += 256) As[e >> 5][e & 31] = A[bh * 1024 + e];
    __syncthreads();
    int n = blockIdx.x * 256 + tid;
    const float* vb = kv + ((size_t)b * 2 * CC + CC + h * CHD) * HW + n;
    float vr[32];
#pragma unroll
    for (int d = 0; d < 32; d++) vr[d] = vb[(size_t)d * HW];
    size_t ob = ((size_t)b * CC + h * CHD) * HW + n;
#pragma unroll
    for (int c = 0; c < 32; c++) {
        float s = 0.f;
#pragma unroll
        for (int d = 0; d < 32; d++) s += As[c][d] * vr[d];
        u16 hv = bfb(s);
        oh[ob + (size_t)c * HW] = hv;
        ol[ob + (size_t)c * HW] = bfb(s - bff(hv));
    }
}

// ---------------- avg pool 2x2 (fp32 + planes) ----------------
__global__ void avgpool_kernel(const float* __restrict__ x, float* __restrict__ o,
                               u16* __restrict__ oh, u16* __restrict__ ol)
{
    int idx = blockIdx.x * 256 + threadIdx.x;
    if (idx >= HB * CC * HW2) return;
    int xx = idx & 127;
    int yy = (idx >> 7) & 127;
    int bc = idx >> 14;
    const float* p = x + (size_t)bc * HW + (yy * 2) * 256 + xx * 2;
    float v = 0.25f * (p[0] + p[1] + p[256] + p[257]);
    o[idx] = v;
    u16 h = bfb(v);
    oh[idx] = h;
    ol[idx] = bfb(v - bff(h));
}

// ---------------- q1 regrouping gather ----------------
__global__ void q1gather_kernel(const float* __restrict__ qt, float* __restrict__ qr)
{
    int idx = blockIdx.x * 256 + threadIdx.x;
    if (idx >= 16 * CC * HW2) return;
    int x = idx & 127;
    int y = (idx >> 7) & 127;
    int c = (idx >> 14) % CC;
    int img = idx / (CC * HW2);
    int whp = y >> 3, yy = y & 7, wwp = x >> 3, xx = x & 7;
    int k = img & 3, b = img >> 2;
    int wh = 8 * k + (whp >> 1);
    int ww = ((whp & 1) << 4) + wwp;
    int sy = wh * 8 + yy, sx = ww * 8 + xx;
    qr[idx] = qt[((size_t)b * CC + c) * HW + sy * 256 + sx];
}

// ---------------- shifted-window cosine attention (register-tiled, conflict-free) ----------------
#define ATS 68
// smem floats: qs 12288 | ks 12288 | vs 12288 | os 12288 | at 64*68 | inq 384 | ink 384 | rpbs 1352 | lab 64
#define WATT_SMEM ((12288 * 4 + 64 * ATS + 384 + 384 + 1352 + 64) * 4)

__global__ void winattn_kernel(const float* __restrict__ qg, const float* __restrict__ kvg,
                               const float* __restrict__ rpbt, const float* __restrict__ temp1,
                               u16* __restrict__ oh, u16* __restrict__ ol)
{
    extern __shared__ float smw[];
    float* qs = smw;                       // 192*64
    float* ks = qs + 12288;
    float* vs = ks + 12288;
    float* os = vs + 12288;
    float* at = os + 12288;                // 64*ATS
    float* inq = at + 64 * ATS;            // 384
    float* ink = inq + 384;                // 384
    float* rpbs = ink + 384;               // 1350 (padded 1352)
    int* lab = (int*)(rpbs + 1352);        // 64

    int win = blockIdx.x;
    int img = win >> 8;
    int loc = win & 255;
    int whp = loc >> 4, wwp = loc & 15;
    int kwin = win >> 2;
    int bk = kwin >> 8;
    int loc2 = kwin & 255;
    int gh = loc2 >> 4, gw = loc2 & 15;
    int tid = threadIdx.x;

    for (int e = tid; e < 192 * 64; e += 256) {
        int c = e >> 6, t = e & 63;
        int yy = t >> 3, xx = t & 7;
        int y = (whp * 8 + yy + 4) & 127;
        int x = (wwp * 8 + xx + 4) & 127;
        qs[e] = qg[((size_t)img * CC + c) * HW2 + y * 128 + x];
    }
    for (int e = tid; e < 192 * 64; e += 256) {
        int c = e >> 6, t = e & 63;
        int yy = t >> 3, xx = t & 7;
        int y = (gh * 8 + yy + 4) & 127;
        int x = (gw * 8 + xx + 4) & 127;
        size_t base = ((size_t)bk * 2 * CC + c) * HW2 + y * 128 + x;
        ks[e] = kvg[base];
        vs[e] = kvg[base + (size_t)CC * HW2];
    }
    for (int e = tid; e < 1350; e += 256) {
        int hh = e / 225, ridx = e - hh * 225;
        rpbs[e] = rpbt[ridx * HEADS + hh];
    }
    if (tid < 64) {
        int yy = tid >> 3, xx = tid & 7;
        int py = gh * 8 + yy, px = gw * 8 + xx;
        lab[tid] = (py < 120 ? 0 : (py < 124 ? 1 : 2)) * 3 + (px < 120 ? 0 : (px < 124 ? 1 : 2));
    }
    __syncthreads();

    for (int e = tid; e < 384; e += 256) {
        int h = e >> 6, t = e & 63;
        float sq = 0.f, sk = 0.f;
#pragma unroll
        for (int i = 0; i < 32; i++) {
            float a = qs[(h * 32 + i) * 64 + t]; sq += a * a;
            float b = ks[(h * 32 + i) * 64 + t]; sk += b * b;
        }
        inq[e] = 1.f / fmaxf(sqrtf(sq), 1e-12f);
        ink[e] = 1.f / fmaxf(sqrtf(sk), 1e-12f);
    }
    __syncthreads();

    const int ng = tid >> 4, mg = tid & 15;       // logits tile ids
    const int n0L = ng * 4, m0L = mg * 4;
    const int i0A = (tid >> 4) * 2;               // AV: 2 channels
    const int nVg = tid & 15;                     // AV: n = nVg + 16*j

    for (int h = 0; h < HEADS; h++) {
        float tmp = temp1[h];
        // ---- logits: 4n x 4m per thread, float4 reads, conflict-free ----
        {
            float a[4][4];
#pragma unroll
            for (int r = 0; r < 4; r++)
#pragma unroll
                for (int c = 0; c < 4; c++) a[r][c] = 0.f;
            const float* qp = qs + h * 2048 + n0L;
            const float* kp = ks + h * 2048 + m0L;
#pragma unroll
            for (int i = 0; i < 32; i++) {
                float4 qv = *(const float4*)(qp + i * 64);
                float4 kv4 = *(const float4*)(kp + i * 64);
                float qa[4] = {qv.x, qv.y, qv.z, qv.w};
                float ka[4] = {kv4.x, kv4.y, kv4.z, kv4.w};
#pragma unroll
                for (int r = 0; r < 4; r++)
#pragma unroll
                    for (int c = 0; c < 4; c++) a[r][c] = fmaf(qa[r], ka[c], a[r][c]);
            }
#pragma unroll
            for (int r = 0; r < 4; r++) {
                int n = n0L + r;
                int yn = n >> 3, xn = n & 7;
                int ln = lab[n];
                float qn = inq[h * 64 + n] * tmp;
                float4 row;
                float* rp = (float*)&row;
#pragma unroll
                for (int c = 0; c < 4; c++) {
                    int m = m0L + c;
                    int ym = m >> 3, xm = m & 7;
                    float s = a[r][c] * qn * ink[h * 64 + m]
                            + rpbs[h * 225 + (yn - ym + 7) * 15 + (xn - xm + 7)];
                    if (ln != lab[m]) s -= 100.f;
                    rp[c] = s;
                }
                *(float4*)(at + n * ATS + m0L) = row;
            }
        }
        __syncthreads();
        // ---- row softmax with FMA-pipe exp ----
        {
            int wid = tid >> 5, lane = tid & 31;
            for (int r = wid; r < 64; r += 8) {
                float v0 = at[r * ATS + lane], v1 = at[r * ATS + lane + 32];
                float mx = fmaxf(v0, v1);
#pragma unroll
                for (int o = 16; o; o >>= 1) mx = fmaxf(mx, __shfl_xor_sync(0xffffffffu, mx, o));
                v0 = fexp(v0 - mx);
                v1 = fexp(v1 - mx);
                float su = v0 + v1;
#pragma unroll
                for (int o = 16; o; o >>= 1) su += __shfl_xor_sync(0xffffffffu, su, o);
                float inv = 1.f / su;
                at[r * ATS + lane] = v0 * inv;
                at[r * ATS + lane + 32] = v1 * inv;
            }
        }
        __syncthreads();
        // ---- AV: 2 channels x 4 n-rows (n = nVg + 16j), float4 reads, conflict-free ----
        {
            float o2[2][4];
#pragma unroll
            for (int j = 0; j < 4; j++) { o2[0][j] = 0.f; o2[1][j] = 0.f; }
            const float* vb0 = vs + (h * 32 + i0A) * 64;
            const float* ab = at + nVg * ATS;
#pragma unroll
            for (int m4 = 0; m4 < 16; m4++) {
                float4 v0 = *(const float4*)(vb0 + m4 * 4);
                float4 v1 = *(const float4*)(vb0 + 64 + m4 * 4);
#pragma unroll
                for (int j = 0; j < 4; j++) {
                    float4 aj = *(const float4*)(ab + j * 16 * ATS + m4 * 4);
                    o2[0][j] += v0.x * aj.x + v0.y * aj.y + v0.z * aj.z + v0.w * aj.w;
                    o2[1][j] += v1.x * aj.x + v1.y * aj.y + v1.z * aj.z + v1.w * aj.w;
                }
            }
#pragma unroll
            for (int i = 0; i < 2; i++)
#pragma unroll
                for (int j = 0; j < 4; j++)
                    os[(h * 32 + i0A + i) * 64 + nVg + 16 * j] = o2[i][j];
        }
        __syncthreads();
    }
    // coalesced plane writes
    for (int e = tid; e < 192 * 64; e += 256) {
        int c = e >> 6, t = e & 63;
        float v = os[e];
        u16 hv = bfb(v);
        size_t o = (size_t)c * 262144 + (size_t)win * 64 + t;
        oh[o] = hv;
        ol[o] = bfb(v - bff(hv));
    }
}

// ---------------- proj1 result scatter-add ----------------
__global__ void scatter1_kernel(const float* __restrict__ pin, float* __restrict__ out)
{
    int idx = blockIdx.x * 256 + threadIdx.x;
    if (idx >= CC * 262144) return;
    int p = idx & 262143;
    int cc = idx >> 18;
    int w = p >> 6;
    int t = p & 63;
    int yy = t >> 3, xx = t & 7;
    int b = w >> 10;
    int wh = (w >> 5) & 31;
    int wn = w & 31;
    int y = (wh * 8 + yy + 4) & 255;
    int x = (wn * 8 + xx + 4) & 255;
    out[((size_t)b * CC + cc) * HW + y * 256 + x] += pin[idx];
}

// ==================================================================
extern "C" void kernel_launch(void* const* d_in, const int* in_sizes, int n_in,
                              void* d_out, int out_size)
{
    const float* x      = (const float*)d_in[0];
    const float* Wq0    = (const float*)d_in[1];
    const float* Wqdw0  = (const float*)d_in[2];
    const float* Wkv0   = (const float*)d_in[3];
    const float* Wkvdw0 = (const float*)d_in[4];
    const float* Wq1    = (const float*)d_in[5];
    const float* Wqdw1  = (const float*)d_in[6];
    const float* Wkv1   = (const float*)d_in[7];
    const float* Wkvdw1 = (const float*)d_in[8];
    const float* Wproj0 = (const float*)d_in[9];
    const float* Wproj1 = (const float*)d_in[10];
    const float* temp0  = (const float*)d_in[11];
    const float* temp1  = (const float*)d_in[12];
    const float* rpbt   = (const float*)d_in[13];
    const float* Wds    = (const float*)d_in[14];
    float* out = (float*)d_out;

    float *A, *B, *invq, *invk, *Sb, *A0, *part;
    u16 *Xh, *Xl, *Wh, *Wl;
    cudaGetSymbolAddress((void**)&A, g_A);
    cudaGetSymbolAddress((void**)&B, g_B);
    cudaGetSymbolAddress((void**)&Xh, g_Xh);
    cudaGetSymbolAddress((void**)&Xl, g_Xl);
    cudaGetSymbolAddress((void**)&Wh, g_Wh);
    cudaGetSymbolAddress((void**)&Wl, g_Wl);
    cudaGetSymbolAddress((void**)&invq, g_invq);
    cudaGetSymbolAddress((void**)&invk, g_invk);
    cudaGetSymbolAddress((void**)&Sb, g_S);
    cudaGetSymbolAddress((void**)&A0, g_A0);
    cudaGetSymbolAddress((void**)&part, g_part);

    const size_t OFF50 = 50331648;
    float* A2 = A + OFF50;

    float* poolF = B;
    u16* poolH = (u16*)(B + 12582912);
    u16* poolL = (u16*)(B + 12582912 + 6291456);
    u16* xdsH  = (u16*)(B + 25165824);
    u16* xdsL  = (u16*)(B + 31457280);
    float* kv1t = B + 37748736;
    float* kv1  = B + 62914560;
    u16* P0h = (u16*)A;
    u16* P0l = (u16*)(A + 25165824);
    u16* W1h = (u16*)B;
    u16* W1l = (u16*)(B + 25165824);

    cudaFuncSetAttribute(mma_gemm2, cudaFuncAttributeMaxDynamicSharedMemorySize, GEMM_SMEM);

    // ---- conversions ----
    cvtw_kernel<<<(256 * CC + 255) / 256, 256>>>(Wq0,    Wh + WO_Q0,  Wl + WO_Q0,  192, 256);
    cvtw_kernel<<<(384 * CC + 255) / 256, 256>>>(Wkv0,   Wh + WO_KV0, Wl + WO_KV0, 384, 384);
    cvtw_kernel<<<(256 * CC + 255) / 256, 256>>>(Wq1,    Wh + WO_Q1,  Wl + WO_Q1,  192, 256);
    cvtw_kernel<<<(384 * CC + 255) / 256, 256>>>(Wkv1,   Wh + WO_KV1, Wl + WO_KV1, 384, 384);
    cvtw_kernel<<<(256 * CC + 255) / 256, 256>>>(Wproj0, Wh + WO_P0,  Wl + WO_P0,  192, 256);
    cvtw_kernel<<<(256 * CC + 255) / 256, 256>>>(Wproj1, Wh + WO_P1,  Wl + WO_P1,  192, 256);
    cvtw_kernel<<<(256 * CC + 255) / 256, 256>>>(Wds,    Wh + WO_DS,  Wl + WO_DS,  192, 256);
    cvtx_kernel<<<49152, 256>>>(x, Xh, Xl, 12582912);

    // ---------- level 0 ----------
    mma_gemm2<<<dim3(512, 3, 4), 256, GEMM_SMEM>>>(Xh, Xl, Wh + WO_KV0, Wl + WO_KV0,
                                                   nullptr, A, nullptr, nullptr, 2 * CC, HW);
    dw3v_kernel<<<(4 * 2 * CC * HW / 4) / 256, 256>>>(A, Wkvdw0, B, 2 * CC, 256, 256, 4 * 2 * CC * HW / 4);
    mma_gemm2<<<dim3(512, 2, 4), 256, GEMM_SMEM>>>(Xh, Xl, Wh + WO_Q0, Wl + WO_Q0,
                                                   nullptr, A, nullptr, nullptr, CC, HW);
    dw3v_kernel<<<(4 * CC * HW / 4) / 256, 256>>>(A, Wqdw0, A2, CC, 256, 256, 4 * CC * HW / 4);
    rownorm_kernel<<<768, 256>>>(A2, CC, invq);
    rownorm_kernel<<<768, 256>>>(B, 2 * CC, invk);
    s_accum_kernel<<<dim3(32, 24), 256>>>(A2, B, part);
    s_reduce_kernel<<<96, 256>>>(part, Sb);
    softmax0_kernel<<<24, dim3(32, 32)>>>(Sb, invq, invk, temp0, A0);
    out0n_kernel<<<dim3(256, 24), 256>>>(A0, B, P0h, P0l);
    mma_gemm2<<<dim3(512, 2, 4), 256, GEMM_SMEM>>>(P0h, P0l, Wh + WO_P0, Wl + WO_P0,
                                                   nullptr, out, nullptr, nullptr, CC, HW);

    // ---------- level 1 ----------
    avgpool_kernel<<<(4 * CC * HW2) / 256, 256>>>(x, poolF, poolH, poolL);
    mma_gemm2<<<dim3(128, 2, 4), 256, GEMM_SMEM>>>(poolH, poolL, Wh + WO_DS, Wl + WO_DS,
                                                   poolF, nullptr, xdsH, xdsL, CC, HW2);
    mma_gemm2<<<dim3(128, 3, 4), 256, GEMM_SMEM>>>(xdsH, xdsL, Wh + WO_KV1, Wl + WO_KV1,
                                                   nullptr, kv1t, nullptr, nullptr, 2 * CC, HW2);
    dw3v_kernel<<<(4 * 2 * CC * HW2 / 4) / 256, 256>>>(kv1t, Wkvdw1, kv1, 2 * CC, 128, 128, 4 * 2 * CC * HW2 / 4);
    mma_gemm2<<<dim3(512, 2, 4), 256, GEMM_SMEM>>>(Xh, Xl, Wh + WO_Q1, Wl + WO_Q1,
                                                   nullptr, A, nullptr, nullptr, CC, HW);
    q1gather_kernel<<<(16 * CC * HW2) / 256, 256>>>(A, A2);
    dw3v_kernel<<<(16 * CC * HW2 / 4) / 256, 256>>>(A2, Wqdw1, A, CC, 128, 128, 16 * CC * HW2 / 4);
    {
        cudaFuncSetAttribute(winattn_kernel, cudaFuncAttributeMaxDynamicSharedMemorySize, WATT_SMEM);
        winattn_kernel<<<4096, 256, WATT_SMEM>>>(A, kv1, rpbt, temp1, W1h, W1l);
    }
    mma_gemm2<<<dim3(2048, 2, 1), 256, GEMM_SMEM>>>(W1h, W1l, Wh + WO_P1, Wl + WO_P1,
                                                    nullptr, A2, nullptr, nullptr, CC, 262144);
    scatter1_kernel<<<(CC * 262144) / 256, 256>>>(A2, out);
}

// round 9
// speedup vs baseline: 1.5762x; 1.0351x over previous
#include <cuda_runtime.h>
#include <cuda_bf16.h>
#include <math.h>
#include <stdint.h>

#define HB 4
#define CC 192
#define HW 65536
#define HW2 16384
#define HEADS 6
#define CHD 32

typedef unsigned short u16;

// ---------------- static scratch ----------------
__device__ float g_A[100663296];      // 402 MB
__device__ float g_B[100663296];      // 402 MB
__device__ u16   g_Xh[50331648];
__device__ u16   g_Xl[50331648];
__device__ u16   g_Wh[393216];
__device__ u16   g_Wl[393216];
__device__ float g_invq[768];
__device__ float g_invk[768];
__device__ float g_S[24 * 1024];
__device__ float g_A0[24 * 1024];
__device__ float g_part[32 * 24 * 1024];
__device__ float g_pq[24576];
__device__ float g_pk[24576];

#define WO_Q0    0
#define WO_KV0   49152
#define WO_Q1    122880
#define WO_KV1   172032
#define WO_P0    245760
#define WO_P1    294912
#define WO_DS    344064

// ================= helpers =================
__device__ __forceinline__ u16 bfb(float v) {
    __nv_bfloat16 b = __float2bfloat16(v);
    return *(u16*)&b;
}
__device__ __forceinline__ float bff(u16 s) {
    __nv_bfloat16 b = *(__nv_bfloat16*)&s;
    return __bfloat162float(b);
}
__device__ __forceinline__ uint32_t smem_u32(const void* p) {
    uint32_t a;
    asm("{ .reg .u64 t; cvta.to.shared.u64 t, %1; cvt.u32.u64 %0, t; }" : "=r"(a) : "l"(p));
    return a;
}
__device__ __forceinline__ void mma16816(float* d, const uint32_t* a, const uint32_t* b) {
    asm volatile(
        "mma.sync.aligned.m16n8k16.row.col.f32.bf16.bf16.f32 "
        "{%0,%1,%2,%3}, {%4,%5,%6,%7}, {%8,%9}, {%0,%1,%2,%3};"
        : "+f"(d[0]), "+f"(d[1]), "+f"(d[2]), "+f"(d[3])
        : "r"(a[0]), "r"(a[1]), "r"(a[2]), "r"(a[3]), "r"(b[0]), "r"(b[1]));
}
__device__ __forceinline__ void ldsm4(uint32_t* r, uint32_t addr) {
    asm volatile("ldmatrix.sync.aligned.m8n8.x4.shared.b16 {%0,%1,%2,%3}, [%4];"
        : "=r"(r[0]), "=r"(r[1]), "=r"(r[2]), "=r"(r[3]) : "r"(addr));
}
__device__ __forceinline__ void ldsm4t(uint32_t* r, uint32_t addr) {
    asm volatile("ldmatrix.sync.aligned.m8n8.x4.trans.shared.b16 {%0,%1,%2,%3}, [%4];"
        : "=r"(r[0]), "=r"(r[1]), "=r"(r[2]), "=r"(r[3]) : "r"(addr));
}
__device__ __forceinline__ void cpa16(uint32_t dst, const void* src) {
    asm volatile("cp.async.cg.shared.global [%0], [%1], 16;" :: "r"(dst), "l"(src));
}
#define CP_COMMIT() asm volatile("cp.async.commit_group;" ::: "memory")
#define CP_WAIT0()  asm volatile("cp.async.wait_group 0;" ::: "memory")
#define CP_WAIT1()  asm volatile("cp.async.wait_group 1;" ::: "memory")

// fast exp on FMA pipe
__device__ __forceinline__ float fexp(float x) {
    float t = x * 1.44269504089f;
    t = fmaxf(t, -126.f);
    float fi = rintf(t);
    float f = t - fi;
    float p = 0.00015403530393f;
    p = fmaf(p, f, 0.00133335581464f);
    p = fmaf(p, f, 0.00961812910763f);
    p = fmaf(p, f, 0.05550410866482f);
    p = fmaf(p, f, 0.24022650695910f);
    p = fmaf(p, f, 0.69314718055995f);
    p = fmaf(p, f, 1.0f);
    int i = (int)fi;
    float s = __int_as_float((i + 127) << 23);
    return p * s;
}

// ---------------- conversion kernels ----------------
__global__ void cvtx_kernel(const float* __restrict__ src, u16* __restrict__ hi,
                            u16* __restrict__ lo, int n4)
{
    int i = blockIdx.x * 256 + threadIdx.x;
    if (i >= n4) return;
    float4 v = *(const float4*)(src + (size_t)i * 4);
    u16 h0 = bfb(v.x), h1 = bfb(v.y), h2 = bfb(v.z), h3 = bfb(v.w);
    ushort4 hh = {h0, h1, h2, h3};
    ushort4 ll = {bfb(v.x - bff(h0)), bfb(v.y - bff(h1)), bfb(v.z - bff(h2)), bfb(v.w - bff(h3))};
    *(ushort4*)(hi + (size_t)i * 4) = hh;
    *(ushort4*)(lo + (size_t)i * 4) = ll;
}

__global__ void cvtw_kernel(const float* __restrict__ src, u16* __restrict__ hi,
                            u16* __restrict__ lo, int OC, int rows)
{
    int i = blockIdx.x * 256 + threadIdx.x;
    if (i >= rows * CC) return;
    int r = i / CC;
    float v = (r < OC) ? src[i] : 0.f;
    u16 h = bfb(v);
    hi[i] = h;
    lo[i] = bfb(v - bff(h));
}

// ---------------- pipelined bf16 hi/lo split GEMM ----------------
// mode 0: normal (Yf write / planes via Yh,Yl, +resid)
// mode 2: q1 regroup write (float2 into Yf at (img,c,y,x))
// mode 3: scatter-add into Yf (proj1 window_reverse + roll)
#define ASTR 40
#define BSTR 136
#define A_BUF_U (2 * 128 * ASTR)
#define B_BUF_U (2 * 32 * BSTR)
#define GEMM_SMEM ((2 * A_BUF_U + 2 * B_BUF_U) * 2)

__global__ void __launch_bounds__(256, 2)
mma_gemm2(const u16* __restrict__ Xh, const u16* __restrict__ Xl,
          const u16* __restrict__ Wh, const u16* __restrict__ Wl,
          const float* __restrict__ resid, float* __restrict__ Yf,
          u16* __restrict__ Yh, u16* __restrict__ Yl,
          int OC, int P, int ycnt, int mode)
{
    extern __shared__ u16 smu[];
    const uint32_t sbA = smem_u32(smu);
    const uint32_t sbB = sbA + 2 * A_BUF_U * 2;

    const int tid = threadIdx.x;
    const int warp = tid >> 5, lane = tid & 31;
    const int g4 = lane >> 2, t4 = lane & 3;
    const int wm = warp >> 1, wn = warp & 1;
    const int gz = blockIdx.z;
    const int bx = blockIdx.x / ycnt;
    const int by = blockIdx.x - bx * ycnt;
    const int oc0 = by * 128;
    const int p0 = bx * 128;
    const size_t xoff = (size_t)gz * CC * P + p0;

    float acc[2][8][4];
#pragma unroll
    for (int mt = 0; mt < 2; mt++)
#pragma unroll
        for (int nt = 0; nt < 8; nt++)
#pragma unroll
            for (int e = 0; e < 4; e++) acc[mt][nt][e] = 0.f;

    auto prefetch = [&](int kc, int buf) {
        const int kbase = kc * 32;
        const uint32_t abase = sbA + buf * A_BUF_U * 2;
#pragma unroll
        for (int i = 0; i < 4; i++) {
            int op = tid + i * 256;
            int pl = op >> 9, rem = op & 511;
            int row = rem >> 2, cq = rem & 3;
            const u16* src = (pl ? Wl : Wh) + (size_t)(oc0 + row) * CC + kbase + cq * 8;
            uint32_t dst = abase + (uint32_t)((pl * 128 + row) * ASTR + cq * 8) * 2;
            cpa16(dst, src);
        }
        const uint32_t bbase = sbB + buf * B_BUF_U * 2;
#pragma unroll
        for (int i = 0; i < 4; i++) {
            int op = tid + i * 256;
            int pl = op >> 9, rem = op & 511;
            int row = rem >> 4, cq = rem & 15;
            const u16* src = (pl ? Xl : Xh) + xoff + (size_t)(kbase + row) * P + cq * 8;
            uint32_t dst = bbase + (uint32_t)((pl * 32 + row) * BSTR + cq * 8) * 2;
            cpa16(dst, src);
        }
    };

    prefetch(0, 0);
    CP_COMMIT();

    const int KC = CC / 32;
    for (int kc = 0; kc < KC; kc++) {
        if (kc + 1 < KC) {
            prefetch(kc + 1, (kc + 1) & 1);
            CP_COMMIT();
            CP_WAIT1();
        } else {
            CP_WAIT0();
        }
        __syncthreads();

        const int buf = kc & 1;
        const uint32_t aoff = sbA + buf * A_BUF_U * 2;
        const uint32_t boff = sbB + buf * B_BUF_U * 2;
#pragma unroll
        for (int ks = 0; ks < 2; ks++) {
            const int k0 = ks * 16;
            uint32_t ah[2][4], al[2][4];
#pragma unroll
            for (int mt = 0; mt < 2; mt++) {
                int mrow = wm * 32 + mt * 16 + (lane & 15);
                int kk = k0 + ((lane & 16) >> 1);
                ldsm4(ah[mt], aoff + (uint32_t)(mrow * ASTR + kk) * 2);
                ldsm4(al[mt], aoff + (uint32_t)((128 + mrow) * ASTR + kk) * 2);
            }
#pragma unroll
            for (int np = 0; np < 4; np++) {
                int krow = k0 + (lane & 15);
                int ncol = wn * 64 + np * 16 + ((lane & 16) >> 1);
                uint32_t bh[4], bl[4];
                ldsm4t(bh, boff + (uint32_t)(krow * BSTR + ncol) * 2);
                ldsm4t(bl, boff + (uint32_t)((32 + krow) * BSTR + ncol) * 2);
#pragma unroll
                for (int half = 0; half < 2; half++) {
                    int nt = np * 2 + half;
                    uint32_t* bhp = bh + half * 2;
                    uint32_t* blp = bl + half * 2;
                    mma16816(acc[0][nt], ah[0], bhp);
                    mma16816(acc[1][nt], ah[1], bhp);
                    mma16816(acc[0][nt], ah[0], blp);
                    mma16816(acc[1][nt], ah[1], blp);
                    mma16816(acc[0][nt], al[0], bhp);
                    mma16816(acc[1][nt], al[1], bhp);
                }
            }
        }
        __syncthreads();
    }

#pragma unroll
    for (int mt = 0; mt < 2; mt++) {
        int r0 = oc0 + wm * 32 + mt * 16 + g4;
#pragma unroll
        for (int nt = 0; nt < 8; nt++) {
            int p = p0 + wn * 64 + nt * 8 + t4 * 2;
#pragma unroll
            for (int hrow = 0; hrow < 2; hrow++) {
                int r = r0 + hrow * 8;
                if (r >= OC) continue;
                float v0 = acc[mt][nt][hrow * 2 + 0];
                float v1 = acc[mt][nt][hrow * 2 + 1];
                if (mode == 2) {
                    // q1 regroup: (gz, r, p=sy*256+sx) -> (img, r, y, x)
                    int sy = p >> 8, sx = p & 255;
                    int wh = sy >> 3, yy = sy & 7;
                    int ww = sx >> 3, xx = sx & 7;
                    int k = wh >> 3;
                    int whp = ((wh & 7) << 1) | (ww >> 4);
                    int wwp = ww & 15;
                    int img = gz * 4 + k;
                    size_t o = ((size_t)img * CC + r) * HW2 + (whp * 8 + yy) * 128 + wwp * 8 + xx;
                    *(float2*)(Yf + o) = make_float2(v0, v1);
                } else if (mode == 3) {
                    // proj1 scatter-add: p = w*64 + t
                    int w = p >> 6, t = p & 63;
                    int yy = t >> 3, xx = t & 7;
                    int b = w >> 10;
                    int wh = (w >> 5) & 31;
                    int wn2 = w & 31;
                    int y = (wh * 8 + yy + 4) & 255;
                    int x = (wn2 * 8 + xx + 4) & 255;
                    size_t o = ((size_t)b * CC + r) * HW + y * 256 + x;
                    float2 prev = *(float2*)(Yf + o);
                    *(float2*)(Yf + o) = make_float2(prev.x + v0, prev.y + v1);
                } else {
                    size_t o = ((size_t)gz * OC + r) * P + p;
                    if (resid) { v0 += resid[o]; v1 += resid[o + 1]; }
                    if (Yf) { Yf[o] = v0; Yf[o + 1] = v1; }
                    if (Yh) {
                        u16 h0 = bfb(v0), h1 = bfb(v1);
                        Yh[o] = h0; Yh[o + 1] = h1;
                        Yl[o] = bfb(v0 - bff(h0)); Yl[o + 1] = bfb(v1 - bff(h1));
                    }
                }
            }
        }
    }
}

// ---------------- depthwise 3x3 (4 px / thread) ----------------
__global__ void dw3v_kernel(const float* __restrict__ in, const float* __restrict__ w9,
                            float* __restrict__ out, int C, int Hn, int Wn, int total4)
{
    int idx = blockIdx.x * 256 + threadIdx.x;
    if (idx >= total4) return;
    int wq = Wn >> 2;
    int xg = (idx % wq) << 2;
    int t = idx / wq;
    int y = t % Hn;
    int c = (t / Hn) % C;
    const float* wp = w9 + c * 9;
    const float* rowc = in + (size_t)t * Wn;
    float a0 = 0.f, a1 = 0.f, a2 = 0.f, a3 = 0.f;
#pragma unroll
    for (int dy = -1; dy <= 1; dy++) {
        int yy = y + dy;
        if ((unsigned)yy >= (unsigned)Hn) continue;
        const float* r = rowc + (ptrdiff_t)dy * Wn;
        float4 v = *(const float4*)(r + xg);
        float left = (xg > 0) ? r[xg - 1] : 0.f;
        float right = (xg + 4 < Wn) ? r[xg + 4] : 0.f;
        float w0 = wp[(dy + 1) * 3], w1 = wp[(dy + 1) * 3 + 1], w2 = wp[(dy + 1) * 3 + 2];
        a0 += w0 * left + w1 * v.x + w2 * v.y;
        a1 += w0 * v.x + w1 * v.y + w2 * v.z;
        a2 += w0 * v.y + w1 * v.z + w2 * v.w;
        a3 += w0 * v.z + w1 * v.w + w2 * right;
    }
    *(float4*)(out + (size_t)t * Wn + xg) = make_float4(a0, a1, a2, a3);
}

// ---------------- level-0 S = q k^T + fused row sumsq partials ----------------
__global__ void s_accum_kernel(const float* __restrict__ q, const float* __restrict__ kv,
                               float* __restrict__ part, float* __restrict__ pq,
                               float* __restrict__ pk)
{
    int bh = blockIdx.y;
    int b = bh / HEADS, h = bh % HEADS;
    const float* qb = q + ((size_t)b * CC + h * CHD) * HW;
    const float* kb = kv + ((size_t)b * 2 * CC + h * CHD) * HW;
    int n0 = blockIdx.x * 2048;
    __shared__ float qt[32][65], kt[32][65];
    float acc[4] = {0.f, 0.f, 0.f, 0.f};
    float sqq = 0.f, skk = 0.f;
    int tid = threadIdx.x;
    const int rq = tid >> 3, sub = tid & 7;
    for (int ns = 0; ns < 2048; ns += 64) {
#pragma unroll
        for (int r = 0; r < 8; r++) {
            int e = tid + r * 256;
            int c = e >> 6, nn = e & 63;
            qt[c][nn] = qb[(size_t)c * HW + n0 + ns + nn];
            kt[c][nn] = kb[(size_t)c * HW + n0 + ns + nn];
        }
        __syncthreads();
#pragma unroll
        for (int i = 0; i < 4; i++) {
            int pr = i * 256 + tid;
            int c = pr >> 5, d = pr & 31;
            float a = 0.f;
#pragma unroll
            for (int kk = 0; kk < 64; kk++) a += qt[c][kk] * kt[d][kk];
            acc[i] += a;
        }
        // fused sum-of-squares partials (8 threads per row, 8 cols each)
#pragma unroll
        for (int j = 0; j < 8; j++) {
            float a = qt[rq][sub * 8 + j]; sqq += a * a;
            float b2 = kt[rq][sub * 8 + j]; skk += b2 * b2;
        }
        __syncthreads();
    }
#pragma unroll
    for (int i = 0; i < 4; i++) {
        int pr = i * 256 + tid;
        part[((size_t)blockIdx.x * 24 + bh) * 1024 + pr] = acc[i];
    }
#pragma unroll
    for (int o = 4; o; o >>= 1) {
        sqq += __shfl_down_sync(0xffffffffu, sqq, o, 8);
        skk += __shfl_down_sync(0xffffffffu, skk, o, 8);
    }
    if (sub == 0) {
        pq[(blockIdx.x * 24 + bh) * 32 + rq] = sqq;
        pk[(blockIdx.x * 24 + bh) * 32 + rq] = skk;
    }
}

__global__ void s_reduce_kernel(const float* __restrict__ part, float* __restrict__ S,
                                const float* __restrict__ pq, const float* __restrict__ pk,
                                float* __restrict__ invq, float* __restrict__ invk)
{
    int idx = blockIdx.x * 256 + threadIdx.x;
    float s = 0.f;
    for (int ck = 0; ck < 32; ck++) s += part[(size_t)ck * 24576 + idx];
    S[idx] = s;
    if (idx < 768) {
        float a = 0.f, b2 = 0.f;
        for (int ck = 0; ck < 32; ck++) {
            a += pq[ck * 768 + idx];
            b2 += pk[ck * 768 + idx];
        }
        invq[idx] = 1.f / fmaxf(sqrtf(a), 1e-12f);
        invk[idx] = 1.f / fmaxf(sqrtf(b2), 1e-12f);
    }
}

// ---------------- level-0 softmax ----------------
__global__ void softmax0_kernel(const float* __restrict__ S, const float* __restrict__ invq,
                                const float* __restrict__ invk, const float* __restrict__ temp0,
                                float* __restrict__ A)
{
    int bh = blockIdx.x;
    int c = threadIdx.y, d = threadIdx.x;
    int b = bh / HEADS, h = bh % HEADS;
    float v = S[bh * 1024 + c * 32 + d] * invq[b * CC + h * CHD + c] *
              invk[b * CC + h * CHD + d] * temp0[h];
    float m = v;
#pragma unroll
    for (int o = 16; o; o >>= 1) m = fmaxf(m, __shfl_xor_sync(0xffffffffu, m, o));
    float e = fexp(v - m);
    float s = e;
#pragma unroll
    for (int o = 16; o; o >>= 1) s += __shfl_xor_sync(0xffffffffu, s, o);
    A[bh * 1024 + c * 32 + d] = e / s;
}

// ---------------- level-0 out = A @ v -> bf16 planes ----------------
__global__ void out0n_kernel(const float* __restrict__ A, const float* __restrict__ kv,
                             u16* __restrict__ oh, u16* __restrict__ ol)
{
    int bh = blockIdx.y;
    int b = bh / HEADS, h = bh % HEADS;
    __shared__ float As[32][33];
    int tid = threadIdx.x;
    for (int e = tid; e < 1024; e += 256) As[e >> 5][e & 31] = A[bh * 1024 + e];
    __syncthreads();
    int n = blockIdx.x * 256 + tid;
    const float* vb = kv + ((size_t)b * 2 * CC + CC + h * CHD) * HW + n;
    float vr[32];
#pragma unroll
    for (int d = 0; d < 32; d++) vr[d] = vb[(size_t)d * HW];
    size_t ob = ((size_t)b * CC + h * CHD) * HW + n;
#pragma unroll
    for (int c = 0; c < 32; c++) {
        float s = 0.f;
#pragma unroll
        for (int d = 0; d < 32; d++) s += As[c][d] * vr[d];
        u16 hv = bfb(s);
        oh[ob + (size_t)c * HW] = hv;
        ol[ob + (size_t)c * HW] = bfb(s - bff(hv));
    }
}

// ---------------- avg pool 2x2 (fp32 + planes) ----------------
__global__ void avgpool_kernel(const float* __restrict__ x, float* __restrict__ o,
                               u16* __restrict__ oh, u16* __restrict__ ol)
{
    int idx = blockIdx.x * 256 + threadIdx.x;
    if (idx >= HB * CC * HW2) return;
    int xx = idx & 127;
    int yy = (idx >> 7) & 127;
    int bc = idx >> 14;
    const float* p = x + (size_t)bc * HW + (yy * 2) * 256 + xx * 2;
    float v = 0.25f * (p[0] + p[1] + p[256] + p[257]);
    o[idx] = v;
    u16 h = bfb(v);
    oh[idx] = h;
    ol[idx] = bfb(v - bff(h));
}

// ---------------- shifted-window cosine attention ----------------
#define ATS 68
#define WATT_SMEM ((12288 * 4 + 64 * ATS + 384 + 384 + 1352 + 64) * 4)

__global__ void winattn_kernel(const float* __restrict__ qg, const float* __restrict__ kvg,
                               const float* __restrict__ rpbt, const float* __restrict__ temp1,
                               u16* __restrict__ oh, u16* __restrict__ ol)
{
    extern __shared__ float smw[];
    float* qs = smw;
    float* ks = qs + 12288;
    float* vs = ks + 12288;
    float* os = vs + 12288;
    float* at = os + 12288;
    float* inq = at + 64 * ATS;
    float* ink = inq + 384;
    float* rpbs = ink + 384;
    int* lab = (int*)(rpbs + 1352);

    int win = blockIdx.x;
    int img = win >> 8;
    int loc = win & 255;
    int whp = loc >> 4, wwp = loc & 15;
    int kwin = win >> 2;
    int bk = kwin >> 8;
    int loc2 = kwin & 255;
    int gh = loc2 >> 4, gw = loc2 & 15;
    int tid = threadIdx.x;

    for (int e = tid; e < 192 * 64; e += 256) {
        int c = e >> 6, t = e & 63;
        int yy = t >> 3, xx = t & 7;
        int y = (whp * 8 + yy + 4) & 127;
        int x = (wwp * 8 + xx + 4) & 127;
        qs[e] = qg[((size_t)img * CC + c) * HW2 + y * 128 + x];
    }
    for (int e = tid; e < 192 * 64; e += 256) {
        int c = e >> 6, t = e & 63;
        int yy = t >> 3, xx = t & 7;
        int y = (gh * 8 + yy + 4) & 127;
        int x = (gw * 8 + xx + 4) & 127;
        size_t base = ((size_t)bk * 2 * CC + c) * HW2 + y * 128 + x;
        ks[e] = kvg[base];
        vs[e] = kvg[base + (size_t)CC * HW2];
    }
    for (int e = tid; e < 1350; e += 256) {
        int hh = e / 225, ridx = e - hh * 225;
        rpbs[e] = rpbt[ridx * HEADS + hh];
    }
    if (tid < 64) {
        int yy = tid >> 3, xx = tid & 7;
        int py = gh * 8 + yy, px = gw * 8 + xx;
        lab[tid] = (py < 120 ? 0 : (py < 124 ? 1 : 2)) * 3 + (px < 120 ? 0 : (px < 124 ? 1 : 2));
    }
    __syncthreads();

    for (int e = tid; e < 384; e += 256) {
        int h = e >> 6, t = e & 63;
        float sq = 0.f, sk = 0.f;
#pragma unroll
        for (int i = 0; i < 32; i++) {
            float a = qs[(h * 32 + i) * 64 + t]; sq += a * a;
            float b = ks[(h * 32 + i) * 64 + t]; sk += b * b;
        }
        inq[e] = 1.f / fmaxf(sqrtf(sq), 1e-12f);
        ink[e] = 1.f / fmaxf(sqrtf(sk), 1e-12f);
    }
    __syncthreads();

    const int ng = tid >> 4, mg = tid & 15;
    const int n0L = ng * 4, m0L = mg * 4;
    const int i0A = (tid >> 4) * 2;
    const int nVg = tid & 15;

    for (int h = 0; h < HEADS; h++) {
        float tmp = temp1[h];
        {
            float a[4][4];
#pragma unroll
            for (int r = 0; r < 4; r++)
#pragma unroll
                for (int c = 0; c < 4; c++) a[r][c] = 0.f;
            const float* qp = qs + h * 2048 + n0L;
            const float* kp = ks + h * 2048 + m0L;
#pragma unroll
            for (int i = 0; i < 32; i++) {
                float4 qv = *(const float4*)(qp + i * 64);
                float4 kv4 = *(const float4*)(kp + i * 64);
                float qa[4] = {qv.x, qv.y, qv.z, qv.w};
                float ka[4] = {kv4.x, kv4.y, kv4.z, kv4.w};
#pragma unroll
                for (int r = 0; r < 4; r++)
#pragma unroll
                    for (int c = 0; c < 4; c++) a[r][c] = fmaf(qa[r], ka[c], a[r][c]);
            }
#pragma unroll
            for (int r = 0; r < 4; r++) {
                int n = n0L + r;
                int yn = n >> 3, xn = n & 7;
                int ln = lab[n];
                float qn = inq[h * 64 + n] * tmp;
                float4 row;
                float* rp = (float*)&row;
#pragma unroll
                for (int c = 0; c < 4; c++) {
                    int m = m0L + c;
                    int ym = m >> 3, xm = m & 7;
                    float s = a[r][c] * qn * ink[h * 64 + m]
                            + rpbs[h * 225 + (yn - ym + 7) * 15 + (xn - xm + 7)];
                    if (ln != lab[m]) s -= 100.f;
                    rp[c] = s;
                }
                *(float4*)(at + n * ATS + m0L) = row;
            }
        }
        __syncthreads();
        {
            int wid = tid >> 5, lane = tid & 31;
            for (int r = wid; r < 64; r += 8) {
                float v0 = at[r * ATS + lane], v1 = at[r * ATS + lane + 32];
                float mx = fmaxf(v0, v1);
#pragma unroll
                for (int o = 16; o; o >>= 1) mx = fmaxf(mx, __shfl_xor_sync(0xffffffffu, mx, o));
                v0 = fexp(v0 - mx);
                v1 = fexp(v1 - mx);
                float su = v0 + v1;
#pragma unroll
                for (int o = 16; o; o >>= 1) su += __shfl_xor_sync(0xffffffffu, su, o);
                float inv = 1.f / su;
                at[r * ATS + lane] = v0 * inv;
                at[r * ATS + lane + 32] = v1 * inv;
            }
        }
        __syncthreads();
        {
            float o2[2][4];
#pragma unroll
            for (int j = 0; j < 4; j++) { o2[0][j] = 0.f; o2[1][j] = 0.f; }
            const float* vb0 = vs + (h * 32 + i0A) * 64;
            const float* ab = at + nVg * ATS;
#pragma unroll
            for (int m4 = 0; m4 < 16; m4++) {
                float4 v0 = *(const float4*)(vb0 + m4 * 4);
                float4 v1 = *(const float4*)(vb0 + 64 + m4 * 4);
#pragma unroll
                for (int j = 0; j < 4; j++) {
                    float4 aj = *(const float4*)(ab + j * 16 * ATS + m4 * 4);
                    o2[0][j] += v0.x * aj.x + v0.y * aj.y + v0.z * aj.z + v0.w * aj.w;
                    o2[1][j] += v1.x * aj.x + v1.y * aj.y + v1.z * aj.z + v1.w * aj.w;
                }
            }
#pragma unroll
            for (int i = 0; i < 2; i++)
#pragma unroll
                for (int j = 0; j < 4; j++)
                    os[(h * 32 + i0A + i) * 64 + nVg + 16 * j] = o2[i][j];
        }
        __syncthreads();
    }
    for (int e = tid; e < 192 * 64; e += 256) {
        int c = e >> 6, t = e & 63;
        float v = os[e];
        u16 hv = bfb(v);
        size_t o = (size_t)c * 262144 + (size_t)win * 64 + t;
        oh[o] = hv;
        ol[o] = bfb(v - bff(hv));
    }
}

// ==================================================================
extern "C" void kernel_launch(void* const* d_in, const int* in_sizes, int n_in,
                              void* d_out, int out_size)
{
    const float* x      = (const float*)d_in[0];
    const float* Wq0    = (const float*)d_in[1];
    const float* Wqdw0  = (const float*)d_in[2];
    const float* Wkv0   = (const float*)d_in[3];
    const float* Wkvdw0 = (const float*)d_in[4];
    const float* Wq1    = (const float*)d_in[5];
    const float* Wqdw1  = (const float*)d_in[6];
    const float* Wkv1   = (const float*)d_in[7];
    const float* Wkvdw1 = (const float*)d_in[8];
    const float* Wproj0 = (const float*)d_in[9];
    const float* Wproj1 = (const float*)d_in[10];
    const float* temp0  = (const float*)d_in[11];
    const float* temp1  = (const float*)d_in[12];
    const float* rpbt   = (const float*)d_in[13];
    const float* Wds    = (const float*)d_in[14];
    float* out = (float*)d_out;

    float *A, *B, *invq, *invk, *Sb, *A0, *part, *pq, *pk;
    u16 *Xh, *Xl, *Wh, *Wl;
    cudaGetSymbolAddress((void**)&A, g_A);
    cudaGetSymbolAddress((void**)&B, g_B);
    cudaGetSymbolAddress((void**)&Xh, g_Xh);
    cudaGetSymbolAddress((void**)&Xl, g_Xl);
    cudaGetSymbolAddress((void**)&Wh, g_Wh);
    cudaGetSymbolAddress((void**)&Wl, g_Wl);
    cudaGetSymbolAddress((void**)&invq, g_invq);
    cudaGetSymbolAddress((void**)&invk, g_invk);
    cudaGetSymbolAddress((void**)&Sb, g_S);
    cudaGetSymbolAddress((void**)&A0, g_A0);
    cudaGetSymbolAddress((void**)&part, g_part);
    cudaGetSymbolAddress((void**)&pq, g_pq);
    cudaGetSymbolAddress((void**)&pk, g_pk);

    const size_t OFF50 = 50331648;
    float* A2 = A + OFF50;

    float* poolF = B;
    u16* poolH = (u16*)(B + 12582912);
    u16* poolL = (u16*)(B + 12582912 + 6291456);
    u16* xdsH  = (u16*)(B + 25165824);
    u16* xdsL  = (u16*)(B + 31457280);
    float* kv1t = B + 37748736;
    float* kv1  = B + 62914560;
    u16* P0h = (u16*)A;
    u16* P0l = (u16*)(A + 25165824);
    u16* W1h = (u16*)B;
    u16* W1l = (u16*)(B + 25165824);

    cudaFuncSetAttribute(mma_gemm2, cudaFuncAttributeMaxDynamicSharedMemorySize, GEMM_SMEM);

    // ---- conversions ----
    cvtw_kernel<<<(256 * CC + 255) / 256, 256>>>(Wq0,    Wh + WO_Q0,  Wl + WO_Q0,  192, 256);
    cvtw_kernel<<<(384 * CC + 255) / 256, 256>>>(Wkv0,   Wh + WO_KV0, Wl + WO_KV0, 384, 384);
    cvtw_kernel<<<(256 * CC + 255) / 256, 256>>>(Wq1,    Wh + WO_Q1,  Wl + WO_Q1,  192, 256);
    cvtw_kernel<<<(384 * CC + 255) / 256, 256>>>(Wkv1,   Wh + WO_KV1, Wl + WO_KV1, 384, 384);
    cvtw_kernel<<<(256 * CC + 255) / 256, 256>>>(Wproj0, Wh + WO_P0,  Wl + WO_P0,  192, 256);
    cvtw_kernel<<<(256 * CC + 255) / 256, 256>>>(Wproj1, Wh + WO_P1,  Wl + WO_P1,  192, 256);
    cvtw_kernel<<<(256 * CC + 255) / 256, 256>>>(Wds,    Wh + WO_DS,  Wl + WO_DS,  192, 256);
    cvtx_kernel<<<49152, 256>>>(x, Xh, Xl, 12582912);

    // ---------- level 0 ----------
    mma_gemm2<<<dim3(512 * 3, 1, 4), 256, GEMM_SMEM>>>(Xh, Xl, Wh + WO_KV0, Wl + WO_KV0,
                                                       nullptr, A, nullptr, nullptr, 2 * CC, HW, 3, 0);
    dw3v_kernel<<<(4 * 2 * CC * HW / 4) / 256, 256>>>(A, Wkvdw0, B, 2 * CC, 256, 256, 4 * 2 * CC * HW / 4);
    mma_gemm2<<<dim3(512 * 2, 1, 4), 256, GEMM_SMEM>>>(Xh, Xl, Wh + WO_Q0, Wl + WO_Q0,
                                                       nullptr, A, nullptr, nullptr, CC, HW, 2, 0);
    dw3v_kernel<<<(4 * CC * HW / 4) / 256, 256>>>(A, Wqdw0, A2, CC, 256, 256, 4 * CC * HW / 4);
    s_accum_kernel<<<dim3(32, 24), 256>>>(A2, B, part, pq, pk);
    s_reduce_kernel<<<96, 256>>>(part, Sb, pq, pk, invq, invk);
    softmax0_kernel<<<24, dim3(32, 32)>>>(Sb, invq, invk, temp0, A0);
    out0n_kernel<<<dim3(256, 24), 256>>>(A0, B, P0h, P0l);
    mma_gemm2<<<dim3(512 * 2, 1, 4), 256, GEMM_SMEM>>>(P0h, P0l, Wh + WO_P0, Wl + WO_P0,
                                                       nullptr, out, nullptr, nullptr, CC, HW, 2, 0);

    // ---------- level 1 ----------
    avgpool_kernel<<<(4 * CC * HW2) / 256, 256>>>(x, poolF, poolH, poolL);
    mma_gemm2<<<dim3(128 * 2, 1, 4), 256, GEMM_SMEM>>>(poolH, poolL, Wh + WO_DS, Wl + WO_DS,
                                                       poolF, nullptr, xdsH, xdsL, CC, HW2, 2, 0);
    mma_gemm2<<<dim3(128 * 3, 1, 4), 256, GEMM_SMEM>>>(xdsH, xdsL, Wh + WO_KV1, Wl + WO_KV1,
                                                       nullptr, kv1t, nullptr, nullptr, 2 * CC, HW2, 3, 0);
    dw3v_kernel<<<(4 * 2 * CC * HW2 / 4) / 256, 256>>>(kv1t, Wkvdw1, kv1, 2 * CC, 128, 128, 4 * 2 * CC * HW2 / 4);
    // q1 GEMM with fused regroup (writes A2 in (16,C,128,128) layout)
    mma_gemm2<<<dim3(512 * 2, 1, 4), 256, GEMM_SMEM>>>(Xh, Xl, Wh + WO_Q1, Wl + WO_Q1,
                                                       nullptr, A2, nullptr, nullptr, CC, HW, 2, 2);
    dw3v_kernel<<<(16 * CC * HW2 / 4) / 256, 256>>>(A2, Wqdw1, A, CC, 128, 128, 16 * CC * HW2 / 4);
    {
        cudaFuncSetAttribute(winattn_kernel, cudaFuncAttributeMaxDynamicSharedMemorySize, WATT_SMEM);
        winattn_kernel<<<4096, 256, WATT_SMEM>>>(A, kv1, rpbt, temp1, W1h, W1l);
    }
    // proj1 GEMM with fused scatter-add into out
    mma_gemm2<<<dim3(2048 * 2, 1, 1), 256, GEMM_SMEM>>>(W1h, W1l, Wh + WO_P1, Wl + WO_P1,
                                                        nullptr, out, nullptr, nullptr, CC, 262144, 2, 3);
}